// round 2
// baseline (speedup 1.0000x reference)
#include <cuda_runtime.h>
#include <math.h>

#define Bz 4
#define Cc 64
#define Hh 96
#define Ww 384
#define BHn (Bz*Hh)          // 384
#define NX (Bz*Cc*Hh*Ww)     // 9437184
#define NLR (Bz*3*Hh*Ww)     // 442368
#define EPS 1e-6f

// ------------------- scratch (device globals; no allocation allowed) -------------------
__device__ __align__(16) float g_Q[2][BHn][Cc][Ww];   // proj1(LN(x)) as [bh][c][w]
__device__ __align__(16) float g_V[2][BHn][Ww][Cc];   // proj2(x) as [bh][w][c]
__device__ __align__(16) float g_A[BHn][Ww][Ww];      // attention logits
__device__ __align__(16) float g_Mr2l[BHn][Ww][Ww];   // softmax rows of A
__device__ __align__(16) float g_MLT[BHn][Ww][Ww];    // MLT[u][w] = M_l2r[w][u]
__device__ float g_rmax[BHn][Ww];
__device__ float g_rinv[BHn][Ww];
__device__ float g_cmax[BHn][Ww];
__device__ float g_cinv[BHn][Ww];
__device__ float g_ms_r2l[BHn][Ww];   // col-sums of M_r2l   -> V_r2l mask
__device__ float g_ms_l2r[BHn][Ww];   // col-sums of M_l2r   -> V_l2r mask

#define NP_CYC (2*BHn*9)
#define NP_PH1 (48*BHn)
#define NP_PH2 (BHn)
#define NP_SM  (2*BHn*24)
__device__ float g_p_cyc[NP_CYC];
__device__ float g_p_ph1[NP_PH1];
__device__ float g_p_ph2[NP_PH2];
__device__ float g_p_smh[NP_SM];
__device__ float g_p_smw[NP_SM];

// =====================================================================================
// K1: fused LayerNorm + both 1x1 projections for one side.
//   Q = P1 @ LN(x): using LN algebra  Q[o,p] = r[p]*(W1' x)[o,p] + (-r[p]*mu[p])*s1[o] + t1[o]
//   with W1'[o,c] = P1[o,c]*nw[c], s1[o]=sum_c W1'[o,c], t1[o]=sum_c P1[o,c]*nb[c]+b1[o]
//   V = P2 @ x + b2
// grid (2, BHn), block 256, dynamic smem
// =====================================================================================
#define PIX 192
__global__ void k1_lnproj(const float* __restrict__ x,
                          const float* __restrict__ nw, const float* __restrict__ nb,
                          const float* __restrict__ p1, const float* __restrict__ b1,
                          const float* __restrict__ p2, const float* __restrict__ b2,
                          int side)
{
    extern __shared__ float sm[];
    float* xs   = sm;                 // [Cc][PIX]
    float* w1   = xs + Cc*PIX;        // [o][c] (scaled)
    float* w2   = w1 + Cc*Cc;         // [o][c]
    float* s1   = w2 + Cc*Cc;         // [o]
    float* t1   = s1 + Cc;            // [o]
    float* mval = t1 + Cc;            // [PIX]  (-r*mu)
    float* rval = mval + PIX;         // [PIX]

    const int bh = blockIdx.y;
    const int b = bh / Hh, h = bh % Hh;
    const int w0 = blockIdx.x * PIX;
    const int tid = threadIdx.x;

    for (int idx = tid; idx < Cc*Cc; idx += 256) {
        int c = idx & 63;
        w1[idx] = p1[idx] * nw[c];
        w2[idx] = p2[idx];
    }
    for (int idx = tid; idx < Cc*PIX; idx += 256) {
        int c = idx / PIX, p = idx % PIX;
        xs[idx] = x[(((long)b*Cc + c)*Hh + h)*Ww + w0 + p];
    }
    __syncthreads();

    for (int o = tid; o < Cc; o += 256) {
        float s = 0.f, t = b1[o];
        for (int c = 0; c < Cc; c++) { s += w1[o*Cc + c]; t += p1[o*Cc + c]*nb[c]; }
        s1[o] = s; t1[o] = t;
    }
    for (int p = tid; p < PIX; p += 256) {
        float s = 0.f, q = 0.f;
        for (int c = 0; c < Cc; c++) { float v = xs[c*PIX + p]; s += v; q += v*v; }
        float mu = s * (1.f/Cc);
        float var = q*(1.f/Cc) - mu*mu;
        float r = rsqrtf(var + EPS);
        rval[p] = r; mval[p] = -r*mu;
    }
    __syncthreads();

    const int tx = tid & 15, ty = tid >> 4;   // tx: 12 pixels strided 16; ty: 4 outs
    float acc[4][12];

    // ---- Q phase ----
    #pragma unroll
    for (int i = 0; i < 4; i++)
        #pragma unroll
        for (int j = 0; j < 12; j++) acc[i][j] = 0.f;
    for (int c = 0; c < Cc; c++) {
        float a0 = w1[(ty*4+0)*Cc+c], a1 = w1[(ty*4+1)*Cc+c];
        float a2 = w1[(ty*4+2)*Cc+c], a3 = w1[(ty*4+3)*Cc+c];
        #pragma unroll
        for (int j = 0; j < 12; j++) {
            float xv = xs[c*PIX + tx + 16*j];
            acc[0][j] += a0*xv; acc[1][j] += a1*xv; acc[2][j] += a2*xv; acc[3][j] += a3*xv;
        }
    }
    #pragma unroll
    for (int i = 0; i < 4; i++) {
        int o = ty*4 + i;
        float so = s1[o], to = t1[o];
        #pragma unroll
        for (int j = 0; j < 12; j++) {
            int p = tx + 16*j;
            g_Q[side][bh][o][w0+p] = rval[p]*acc[i][j] + mval[p]*so + to;
        }
    }

    // ---- V phase ----
    #pragma unroll
    for (int i = 0; i < 4; i++)
        #pragma unroll
        for (int j = 0; j < 12; j++) acc[i][j] = 0.f;
    for (int c = 0; c < Cc; c++) {
        float a0 = w2[(ty*4+0)*Cc+c], a1 = w2[(ty*4+1)*Cc+c];
        float a2 = w2[(ty*4+2)*Cc+c], a3 = w2[(ty*4+3)*Cc+c];
        #pragma unroll
        for (int j = 0; j < 12; j++) {
            float xv = xs[c*PIX + tx + 16*j];
            acc[0][j] += a0*xv; acc[1][j] += a1*xv; acc[2][j] += a2*xv; acc[3][j] += a3*xv;
        }
    }
    float bo0 = b2[ty*4], bo1 = b2[ty*4+1], bo2 = b2[ty*4+2], bo3 = b2[ty*4+3];
    #pragma unroll
    for (int j = 0; j < 12; j++) {
        int p = tx + 16*j;
        float4 vv = make_float4(acc[0][j]+bo0, acc[1][j]+bo1, acc[2][j]+bo2, acc[3][j]+bo3);
        *(float4*)&g_V[side][bh][w0+p][ty*4] = vv;
    }
}

// =====================================================================================
// K2: A[bh][w][v] = 0.125 * sum_c Ql[c][w] * Qr[c][v].  grid (6,6,BHn), block 256
// =====================================================================================
__global__ void k2_attn()
{
    __shared__ float Qa[Cc][64], Qb[Cc][64];
    const int bh = blockIdx.z;
    const int v0 = blockIdx.x * 64, w0 = blockIdx.y * 64;
    const int tid = threadIdx.x;
    for (int idx = tid; idx < Cc*64; idx += 256) {
        int c = idx >> 6, t = idx & 63;
        Qa[c][t] = g_Q[0][bh][c][w0 + t];
        Qb[c][t] = g_Q[1][bh][c][v0 + t];
    }
    __syncthreads();
    const int tx = tid & 15, ty = tid >> 4;
    float acc[4][4] = {};
    for (int c = 0; c < Cc; c++) {
        float4 a = *(float4*)&Qa[c][ty*4];
        float4 bb = *(float4*)&Qb[c][tx*4];
        float av[4] = {a.x, a.y, a.z, a.w};
        float bv[4] = {bb.x, bb.y, bb.z, bb.w};
        #pragma unroll
        for (int i = 0; i < 4; i++)
            #pragma unroll
            for (int j = 0; j < 4; j++) acc[i][j] += av[i]*bv[j];
    }
    const float scale = 0.125f;
    #pragma unroll
    for (int i = 0; i < 4; i++) {
        float4 r = make_float4(acc[i][0]*scale, acc[i][1]*scale, acc[i][2]*scale, acc[i][3]*scale);
        *(float4*)&g_A[bh][w0 + ty*4 + i][v0 + tx*4] = r;
    }
}

// =====================================================================================
// K3a: row stats of A (rmax, rinv).  grid (48, BHn), block 256 (warp per row)
// =====================================================================================
__global__ void k3a_rowstats()
{
    const int bh = blockIdx.y;
    const int w = blockIdx.x*8 + (threadIdx.x >> 5);
    const int lane = threadIdx.x & 31;
    const float* __restrict__ row = g_A[bh][w];
    float m = -1e30f;
    for (int v = lane; v < Ww; v += 32) m = fmaxf(m, row[v]);
    #pragma unroll
    for (int o = 16; o; o >>= 1) m = fmaxf(m, __shfl_xor_sync(0xffffffffu, m, o));
    float s = 0.f;
    for (int v = lane; v < Ww; v += 32) s += __expf(row[v] - m);
    #pragma unroll
    for (int o = 16; o; o >>= 1) s += __shfl_xor_sync(0xffffffffu, s, o);
    if (!lane) { g_rmax[bh][w] = m; g_rinv[bh][w] = 1.f/s; }
}

// =====================================================================================
// K3b: column stats of A (cmax, cinv) + column sums of M_r2l (mask source).
// grid (12, BHn), block 256: 32 columns per block, 8 row-groups.
// =====================================================================================
__global__ void k3b_colstats()
{
    __shared__ float redm[8][32], reds[8][32], redms[8][32];
    const int bh = blockIdx.y;
    const int tid = threadIdx.x;
    const int lane = tid & 31, g = tid >> 5;
    const int v = blockIdx.x*32 + lane;

    float m = -1e30f;
    for (int w = g; w < Ww; w += 8) m = fmaxf(m, g_A[bh][w][v]);
    redm[g][lane] = m;
    __syncthreads();
    if (g == 0) {
        for (int k = 1; k < 8; k++) m = fmaxf(m, redm[k][lane]);
        redm[0][lane] = m;
    }
    __syncthreads();
    m = redm[0][lane];

    float s = 0.f, ms = 0.f;
    for (int w = g; w < Ww; w += 8) {
        float a = g_A[bh][w][v];
        s  += __expf(a - m);
        ms += __expf(a - g_rmax[bh][w]) * g_rinv[bh][w];
    }
    reds[g][lane] = s; redms[g][lane] = ms;
    __syncthreads();
    if (g == 0) {
        for (int k = 1; k < 8; k++) { s += reds[k][lane]; ms += redms[k][lane]; }
        g_cmax[bh][v] = m;
        g_cinv[bh][v] = 1.f/s;
        g_ms_r2l[bh][v] = ms;
    }
}

// =====================================================================================
// K4: write M_r2l and MLT (= M_l2r transposed), accumulate row sums of MLT (mask l2r).
// grid (48, BHn), block 256 (warp per row u)
// =====================================================================================
__global__ void k4_writeM()
{
    const int bh = blockIdx.y;
    const int u = blockIdx.x*8 + (threadIdx.x >> 5);
    const int lane = threadIdx.x & 31;
    const float rm = g_rmax[bh][u], ri = g_rinv[bh][u];
    const float* __restrict__ row = g_A[bh][u];
    float msum = 0.f;
    for (int v = lane; v < Ww; v += 32) {
        float a = row[v];
        g_Mr2l[bh][u][v] = __expf(a - rm) * ri;
        float m2 = __expf(a - g_cmax[bh][v]) * g_cinv[bh][v];
        g_MLT[bh][u][v] = m2;
        msum += m2;
    }
    #pragma unroll
    for (int o = 16; o; o >>= 1) msum += __shfl_xor_sync(0xffffffffu, msum, o);
    if (!lane) g_ms_l2r[bh][u] = msum;
}

// =====================================================================================
// K5: cycle loss. term0: M_lrl = Mr2l @ MLT^T ; term1: M_rlr[w,u] = sum_v MLT[v][w]*Mr2l[v][u]
// 128x128 output tile, k-chunk 16, 8x8 per thread. Accumulate |C*mask - eye*mask|.
// grid (3,3,BHn*2), block 256
// =====================================================================================
#define TK 16
__global__ void __launch_bounds__(256) k5_cycle()
{
    __shared__ float As[TK][132];
    __shared__ float Bs[TK][132];
    __shared__ float red[256];
    const int z = blockIdx.z;
    const int term = z & 1, bh = z >> 1;
    const int u0 = blockIdx.x*128, w0 = blockIdx.y*128;
    const int tid = threadIdx.x;
    const int tx = tid & 15, ty = tid >> 4;
    float acc[8][8] = {};

    for (int vk = 0; vk < Ww; vk += TK) {
        if (term == 0) {
            #pragma unroll
            for (int r = 0; r < 2; r++) {
                int idx = tid + r*256;
                int i = idx >> 2, j = (idx & 3)*4;
                float4 va = *(const float4*)&g_Mr2l[bh][w0+i][vk+j];
                As[j+0][i] = va.x; As[j+1][i] = va.y; As[j+2][i] = va.z; As[j+3][i] = va.w;
                float4 vb = *(const float4*)&g_MLT[bh][u0+i][vk+j];
                Bs[j+0][i] = vb.x; Bs[j+1][i] = vb.y; Bs[j+2][i] = vb.z; Bs[j+3][i] = vb.w;
            }
        } else {
            #pragma unroll
            for (int r = 0; r < 2; r++) {
                int idx = tid + r*256;
                int k = idx >> 5, w = (idx & 31)*4;
                *(float4*)&As[k][w] = *(const float4*)&g_MLT[bh][vk+k][w0+w];
                *(float4*)&Bs[k][w] = *(const float4*)&g_Mr2l[bh][vk+k][u0+w];
            }
        }
        __syncthreads();
        #pragma unroll
        for (int k = 0; k < TK; k++) {
            float a[8], b[8];
            *(float4*)(a)   = *(float4*)&As[k][ty*4];
            *(float4*)(a+4) = *(float4*)&As[k][64 + ty*4];
            *(float4*)(b)   = *(float4*)&Bs[k][tx*4];
            *(float4*)(b+4) = *(float4*)&Bs[k][64 + tx*4];
            #pragma unroll
            for (int i = 0; i < 8; i++)
                #pragma unroll
                for (int j = 0; j < 8; j++) acc[i][j] += a[i]*b[j];
        }
        __syncthreads();
    }

    const float* msrow = (term == 0) ? g_ms_l2r[bh] : g_ms_r2l[bh];
    float lsum = 0.f;
    #pragma unroll
    for (int i = 0; i < 8; i++) {
        int w = w0 + ((i < 4) ? (ty*4 + i) : (64 + ty*4 + i - 4));
        #pragma unroll
        for (int j = 0; j < 8; j++) {
            int u = u0 + ((j < 4) ? (tx*4 + j) : (64 + tx*4 + j - 4));
            float mk = (msrow[u] > 0.1f) ? 1.f : 0.f;
            float e = (w == u) ? 1.f : 0.f;
            lsum += mk * fabsf(acc[i][j] - e);
        }
    }
    red[tid] = lsum; __syncthreads();
    for (int s = 128; s; s >>= 1) { if (tid < s) red[tid] += red[tid+s]; __syncthreads(); }
    if (!tid) g_p_cyc[z*9 + blockIdx.y*3 + blockIdx.x] = red[0];
}

// =====================================================================================
// K6: outputs.  side0: out = x_l + beta*(Mr2l @ V_r) ; side1: out = x_r + gamma*(M_l2r @ V_l)
// 128w x 64c tile, k-chunk 16.  grid (3, BHn), block 256
// =====================================================================================
__global__ void k6_fout(const float* __restrict__ x, const float* __restrict__ bg,
                        float* __restrict__ out, int side)
{
    __shared__ float As[TK][132];
    __shared__ float Vs[TK][68];
    const int bh = blockIdx.y;
    const int b = bh / Hh, h = bh % Hh;
    const int w0 = blockIdx.x * 128;
    const int tid = threadIdx.x;
    const int tx = tid & 15, ty = tid >> 4;
    float acc[8][4] = {};
    const int vside = (side == 0) ? 1 : 0;

    for (int vk = 0; vk < Ww; vk += TK) {
        if (side == 0) {
            #pragma unroll
            for (int r = 0; r < 2; r++) {
                int idx = tid + r*256;
                int i = idx >> 2, j = (idx & 3)*4;
                float4 va = *(const float4*)&g_Mr2l[bh][w0+i][vk+j];
                As[j+0][i] = va.x; As[j+1][i] = va.y; As[j+2][i] = va.z; As[j+3][i] = va.w;
            }
        } else {
            #pragma unroll
            for (int r = 0; r < 2; r++) {
                int idx = tid + r*256;
                int k = idx >> 5, w = (idx & 31)*4;
                *(float4*)&As[k][w] = *(const float4*)&g_MLT[bh][vk+k][w0+w];
            }
        }
        {
            int k = tid >> 4, c4 = (tid & 15)*4;
            *(float4*)&Vs[k][c4] = *(const float4*)&g_V[vside][bh][vk+k][c4];
        }
        __syncthreads();
        #pragma unroll
        for (int k = 0; k < TK; k++) {
            float a[8], bv[4];
            *(float4*)(a)   = *(float4*)&As[k][ty*4];
            *(float4*)(a+4) = *(float4*)&As[k][64 + ty*4];
            *(float4*)(bv)  = *(float4*)&Vs[k][tx*4];
            #pragma unroll
            for (int i = 0; i < 8; i++)
                #pragma unroll
                for (int j = 0; j < 4; j++) acc[i][j] += a[i]*bv[j];
        }
        __syncthreads();
    }
    #pragma unroll
    for (int j = 0; j < 4; j++) {
        int c = tx*4 + j;
        float bgc = bg[c];
        #pragma unroll
        for (int i = 0; i < 8; i++) {
            int w = w0 + ((i < 4) ? (ty*4 + i) : (64 + ty*4 + i - 4));
            long gi = (((long)b*Cc + c)*Hh + h)*Ww + w;
            out[gi] = x[gi] + bgc*acc[i][j];
        }
    }
}

// =====================================================================================
// K7a: LR_r_warp = Mr2l @ LR_right rows + photo term 1 (mask = V_l2r).
// grid (48, BHn), block 256 (warp per output pixel w)
// =====================================================================================
__global__ void k7a_photo1(const float* __restrict__ LRl, const float* __restrict__ LRr)
{
    __shared__ float lr[3][Ww];
    __shared__ float r8[8];
    const int bh = blockIdx.y;
    const int b = bh / Hh, h = bh % Hh;
    const int w = blockIdx.x*8 + (threadIdx.x >> 5);
    const int lane = threadIdx.x & 31;
    for (int idx = threadIdx.x; idx < 3*Ww; idx += 256) {
        int ch = idx / Ww, v = idx % Ww;
        lr[ch][v] = LRr[(((long)b*3 + ch)*Hh + h)*Ww + v];
    }
    __syncthreads();
    float a0 = 0.f, a1 = 0.f, a2 = 0.f;
    const float* __restrict__ mrow = g_Mr2l[bh][w];
    for (int v = lane; v < Ww; v += 32) {
        float m = mrow[v];
        a0 += m*lr[0][v]; a1 += m*lr[1][v]; a2 += m*lr[2][v];
    }
    #pragma unroll
    for (int o = 16; o; o >>= 1) {
        a0 += __shfl_xor_sync(0xffffffffu, a0, o);
        a1 += __shfl_xor_sync(0xffffffffu, a1, o);
        a2 += __shfl_xor_sync(0xffffffffu, a2, o);
    }
    if (!lane) {
        float mk = (g_ms_l2r[bh][w] > 0.1f) ? 1.f : 0.f;
        long base = (((long)b*3)*Hh + h)*Ww + w;
        float part = mk * (fabsf(LRl[base] - a0)
                         + fabsf(LRl[base + (long)Hh*Ww] - a1)
                         + fabsf(LRl[base + 2L*Hh*Ww] - a2));
        r8[threadIdx.x >> 5] = part;
    }
    __syncthreads();
    if (threadIdx.x == 0) {
        float s = 0.f;
        for (int k = 0; k < 8; k++) s += r8[k];
        g_p_ph1[bh*48 + blockIdx.x] = s;
    }
}

// =====================================================================================
// K7b: LR_l_warp[w] = sum_v MLT[v][w]*LR_left[v] + photo term 2 (mask = V_r2l).
// grid (BHn), block 128
// =====================================================================================
__global__ void k7b_photo2(const float* __restrict__ LRl, const float* __restrict__ LRr)
{
    __shared__ float la[3][Ww], lb[3][Ww];
    __shared__ float red[128];
    const int bh = blockIdx.x;
    const int b = bh / Hh, h = bh % Hh;
    const int tid = threadIdx.x;
    for (int idx = tid; idx < 3*Ww; idx += 128) {
        int ch = idx / Ww, w = idx % Ww;
        long gi = (((long)b*3 + ch)*Hh + h)*Ww + w;
        la[ch][w] = LRl[gi];
        lb[ch][w] = LRr[gi];
    }
    __syncthreads();
    float acc[3][3] = {};
    for (int v = 0; v < Ww; v++) {
        const float* __restrict__ mr = g_MLT[bh][v];
        float l0 = la[0][v], l1 = la[1][v], l2 = la[2][v];
        #pragma unroll
        for (int s = 0; s < 3; s++) {
            float m = mr[tid + s*128];
            acc[s][0] += m*l0; acc[s][1] += m*l1; acc[s][2] += m*l2;
        }
    }
    float part = 0.f;
    #pragma unroll
    for (int s = 0; s < 3; s++) {
        int w = tid + s*128;
        float mk = (g_ms_r2l[bh][w] > 0.1f) ? 1.f : 0.f;
        part += mk * (fabsf(lb[0][w] - acc[s][0])
                    + fabsf(lb[1][w] - acc[s][1])
                    + fabsf(lb[2][w] - acc[s][2]));
    }
    red[tid] = part; __syncthreads();
    for (int s = 64; s; s >>= 1) { if (tid < s) red[tid] += red[tid+s]; __syncthreads(); }
    if (!tid) g_p_ph2[bh] = red[0];
}

// =====================================================================================
// K8: smoothness losses over both M matrices (MLT works for M_l2r: same element sets).
// grid (24, BHn, 2), block 256; 16 rows per block.
// =====================================================================================
__global__ void k8_smooth()
{
    __shared__ float redh[256], redw[256];
    const int mat = blockIdx.z, bh = blockIdx.y, w0 = blockIdx.x*16;
    const int h = bh % Hh;
    const float* __restrict__ M = mat ? &g_MLT[0][0][0] : &g_Mr2l[0][0][0];
    const int tid = threadIdx.x;
    float sh = 0.f, sw = 0.f;
    for (int idx = tid; idx < 16*Ww; idx += 256) {
        int w = w0 + idx / Ww, v = idx % Ww;
        long base = ((long)bh*Ww + w)*Ww + v;
        float m = M[base];
        if (h < Hh - 1) sh += fabsf(m - M[base + (long)Ww*Ww]);
        if (w < Ww - 1 && v < Ww - 1) sw += fabsf(m - M[base + Ww + 1]);
    }
    redh[tid] = sh; redw[tid] = sw; __syncthreads();
    for (int s = 128; s; s >>= 1) {
        if (tid < s) { redh[tid] += redh[tid+s]; redw[tid] += redw[tid+s]; }
        __syncthreads();
    }
    if (!tid) {
        int slot = (mat*BHn + bh)*24 + blockIdx.x;
        g_p_smh[slot] = redh[0];
        g_p_smw[slot] = redw[0];
    }
}

// =====================================================================================
// K9: deterministic final reduction (double), writes loss scalar.
// =====================================================================================
__global__ void k9_final(const float* __restrict__ loss_in, float* __restrict__ out_loss)
{
    __shared__ double red[256];
    const int tid = threadIdx.x;
    double acc[4] = {0.0, 0.0, 0.0, 0.0};
    for (int i = tid; i < NP_CYC; i += 256) acc[0] += (double)g_p_cyc[i];
    for (int i = tid; i < NP_PH1; i += 256) acc[1] += (double)g_p_ph1[i];
    for (int i = tid; i < NP_PH2; i += 256) acc[1] += (double)g_p_ph2[i];
    for (int i = tid; i < NP_SM;  i += 256) acc[2] += (double)g_p_smh[i];
    for (int i = tid; i < NP_SM;  i += 256) acc[3] += (double)g_p_smw[i];
    double tot[4];
    for (int a = 0; a < 4; a++) {
        red[tid] = acc[a]; __syncthreads();
        for (int s = 128; s; s >>= 1) { if (tid < s) red[tid] += red[tid+s]; __syncthreads(); }
        tot[a] = red[0]; __syncthreads();
    }
    if (!tid) {
        double lc = tot[0] / ((double)Bz*Hh*Ww*Ww);
        double lp = tot[1] / ((double)Bz*3*Hh*Ww);
        double lh = tot[2] / ((double)Bz*(Hh-1)*Ww*Ww);
        double lw = tot[3] / ((double)Bz*Hh*(Ww-1)*(Ww-1));
        out_loss[0] = (float)((double)loss_in[0] + 0.0025*(lp + 0.1*(lw + lh) + lc));
    }
}

// =====================================================================================
extern "C" void kernel_launch(void* const* d_in, const int* in_sizes, int n_in,
                              void* d_out, int out_size)
{
    (void)in_sizes; (void)n_in; (void)out_size;
    const float* x_l   = (const float*)d_in[0];
    const float* x_r   = (const float*)d_in[1];
    const float* LRl   = (const float*)d_in[2];
    const float* LRr   = (const float*)d_in[3];
    const float* lossi = (const float*)d_in[4];
    const float* nlw = (const float*)d_in[5];
    const float* nlb = (const float*)d_in[6];
    const float* nrw = (const float*)d_in[7];
    const float* nrb = (const float*)d_in[8];
    const float* lp1w = (const float*)d_in[9];
    const float* lp1b = (const float*)d_in[10];
    const float* rp1w = (const float*)d_in[11];
    const float* rp1b = (const float*)d_in[12];
    const float* lp2w = (const float*)d_in[13];
    const float* lp2b = (const float*)d_in[14];
    const float* rp2w = (const float*)d_in[15];
    const float* rp2b = (const float*)d_in[16];
    const float* beta  = (const float*)d_in[17];
    const float* gamma = (const float*)d_in[18];

    float* out = (float*)d_out;
    float* out_xl   = out;
    float* out_xr   = out + NX;
    float* out_lrl  = out + 2L*NX;
    float* out_lrr  = out + 2L*NX + NLR;
    float* out_loss = out + 2L*NX + 2L*NLR;

    const size_t smem1 = (size_t)(Cc*PIX + 2*Cc*Cc + 2*Cc + 2*PIX) * sizeof(float);
    cudaFuncSetAttribute(k1_lnproj, cudaFuncAttributeMaxDynamicSharedMemorySize, (int)smem1);

    k1_lnproj<<<dim3(2, BHn), 256, smem1>>>(x_l, nlw, nlb, lp1w, lp1b, lp2w, lp2b, 0);
    k1_lnproj<<<dim3(2, BHn), 256, smem1>>>(x_r, nrw, nrb, rp1w, rp1b, rp2w, rp2b, 1);
    k2_attn<<<dim3(6, 6, BHn), 256>>>();
    k3a_rowstats<<<dim3(48, BHn), 256>>>();
    k3b_colstats<<<dim3(12, BHn), 256>>>();
    k4_writeM<<<dim3(48, BHn), 256>>>();
    k5_cycle<<<dim3(3, 3, BHn*2), 256>>>();
    k6_fout<<<dim3(3, BHn), 256>>>(x_l, beta, out_xl, 0);
    k6_fout<<<dim3(3, BHn), 256>>>(x_r, gamma, out_xr, 1);
    k7a_photo1<<<dim3(48, BHn), 256>>>(LRl, LRr);
    k7b_photo2<<<BHn, 128>>>(LRl, LRr);
    k8_smooth<<<dim3(24, BHn, 2), 256>>>();
    cudaMemcpyAsync(out_lrl, LRl, (size_t)NLR*sizeof(float), cudaMemcpyDeviceToDevice, 0);
    cudaMemcpyAsync(out_lrr, LRr, (size_t)NLR*sizeof(float), cudaMemcpyDeviceToDevice, 0);
    k9_final<<<1, 256>>>(lossi, out_loss);
}

// round 3
// speedup vs baseline: 1.1288x; 1.1288x over previous
#include <cuda_runtime.h>
#include <math.h>

#define Bz 4
#define Cc 64
#define Hh 96
#define Ww 384
#define BHn (Bz*Hh)
#define NX (Bz*Cc*Hh*Ww)
#define NLR (Bz*3*Hh*Ww)
#define EPS 1e-6f

typedef unsigned long long u64;
__device__ __forceinline__ u64 dup2f(float x) {
    u64 r; asm("mov.b64 %0, {%1, %1};" : "=l"(r) : "f"(x)); return r;
}
__device__ __forceinline__ void fma2(u64 &d, u64 a, u64 b) {
    asm("fma.rn.f32x2 %0, %1, %2, %0;" : "+l"(d) : "l"(a), "l"(b));
}
__device__ __forceinline__ float2 up2(u64 v) {
    float2 r; asm("mov.b64 {%0, %1}, %2;" : "=f"(r.x), "=f"(r.y) : "l"(v)); return r;
}

__device__ __align__(16) float g_Q[2][BHn][Cc][Ww];
__device__ __align__(16) float g_V[2][BHn][Ww][Cc];
__device__ __align__(16) float g_A[BHn][Ww][Ww];
__device__ __align__(16) float g_Mr2l[BHn][Ww][Ww];
__device__ __align__(16) float g_MLT[BHn][Ww][Ww];
__device__ float g_rmax[BHn][Ww];
__device__ float g_rinv[BHn][Ww];
__device__ float g_cmax[BHn][Ww];
__device__ float g_cinv[BHn][Ww];
__device__ float g_ms_r2l[BHn][Ww];
__device__ float g_ms_l2r[BHn][Ww];

#define NP_CYC (2*BHn*9)
#define NP_PH1 (48*BHn)
#define NP_PH2 (BHn)
#define NP_SM  (2*BHn*24)
__device__ float g_p_cyc[NP_CYC];
__device__ float g_p_ph1[NP_PH1];
__device__ float g_p_ph2[NP_PH2];
__device__ float g_p_smh[NP_SM];
__device__ float g_p_smw[NP_SM];

// ================= K1: LN + both 1x1 projections (unchanged from R0) =================
#define PIX 192
__global__ void k1_lnproj(const float* __restrict__ x,
                          const float* __restrict__ nw, const float* __restrict__ nb,
                          const float* __restrict__ p1, const float* __restrict__ b1,
                          const float* __restrict__ p2, const float* __restrict__ b2,
                          int side)
{
    extern __shared__ float sm[];
    float* xs   = sm;
    float* w1   = xs + Cc*PIX;
    float* w2   = w1 + Cc*Cc;
    float* s1   = w2 + Cc*Cc;
    float* t1   = s1 + Cc;
    float* mval = t1 + Cc;
    float* rval = mval + PIX;

    const int bh = blockIdx.y;
    const int b = bh / Hh, h = bh % Hh;
    const int w0 = blockIdx.x * PIX;
    const int tid = threadIdx.x;

    for (int idx = tid; idx < Cc*Cc; idx += 256) {
        int c = idx & 63;
        w1[idx] = p1[idx] * nw[c];
        w2[idx] = p2[idx];
    }
    for (int idx = tid; idx < Cc*PIX; idx += 256) {
        int c = idx / PIX, p = idx % PIX;
        xs[idx] = x[(((long)b*Cc + c)*Hh + h)*Ww + w0 + p];
    }
    __syncthreads();

    for (int o = tid; o < Cc; o += 256) {
        float s = 0.f, t = b1[o];
        for (int c = 0; c < Cc; c++) { s += w1[o*Cc + c]; t += p1[o*Cc + c]*nb[c]; }
        s1[o] = s; t1[o] = t;
    }
    for (int p = tid; p < PIX; p += 256) {
        float s = 0.f, q = 0.f;
        for (int c = 0; c < Cc; c++) { float v = xs[c*PIX + p]; s += v; q += v*v; }
        float mu = s * (1.f/Cc);
        float var = q*(1.f/Cc) - mu*mu;
        float r = rsqrtf(var + EPS);
        rval[p] = r; mval[p] = -r*mu;
    }
    __syncthreads();

    const int tx = tid & 15, ty = tid >> 4;
    float acc[4][12];

    #pragma unroll
    for (int i = 0; i < 4; i++)
        #pragma unroll
        for (int j = 0; j < 12; j++) acc[i][j] = 0.f;
    for (int c = 0; c < Cc; c++) {
        float a0 = w1[(ty*4+0)*Cc+c], a1 = w1[(ty*4+1)*Cc+c];
        float a2 = w1[(ty*4+2)*Cc+c], a3 = w1[(ty*4+3)*Cc+c];
        #pragma unroll
        for (int j = 0; j < 12; j++) {
            float xv = xs[c*PIX + tx + 16*j];
            acc[0][j] += a0*xv; acc[1][j] += a1*xv; acc[2][j] += a2*xv; acc[3][j] += a3*xv;
        }
    }
    #pragma unroll
    for (int i = 0; i < 4; i++) {
        int o = ty*4 + i;
        float so = s1[o], to = t1[o];
        #pragma unroll
        for (int j = 0; j < 12; j++) {
            int p = tx + 16*j;
            g_Q[side][bh][o][w0+p] = rval[p]*acc[i][j] + mval[p]*so + to;
        }
    }

    #pragma unroll
    for (int i = 0; i < 4; i++)
        #pragma unroll
        for (int j = 0; j < 12; j++) acc[i][j] = 0.f;
    for (int c = 0; c < Cc; c++) {
        float a0 = w2[(ty*4+0)*Cc+c], a1 = w2[(ty*4+1)*Cc+c];
        float a2 = w2[(ty*4+2)*Cc+c], a3 = w2[(ty*4+3)*Cc+c];
        #pragma unroll
        for (int j = 0; j < 12; j++) {
            float xv = xs[c*PIX + tx + 16*j];
            acc[0][j] += a0*xv; acc[1][j] += a1*xv; acc[2][j] += a2*xv; acc[3][j] += a3*xv;
        }
    }
    float bo0 = b2[ty*4], bo1 = b2[ty*4+1], bo2 = b2[ty*4+2], bo3 = b2[ty*4+3];
    #pragma unroll
    for (int j = 0; j < 12; j++) {
        int p = tx + 16*j;
        float4 vv = make_float4(acc[0][j]+bo0, acc[1][j]+bo1, acc[2][j]+bo2, acc[3][j]+bo3);
        *(float4*)&g_V[side][bh][w0+p][ty*4] = vv;
    }
}

// ================= K2: attention logits, 128x128 tile, FFMA2 =================
#define TK 16
__global__ void __launch_bounds__(256) k2_attn()
{
    __shared__ float As[TK][132];
    __shared__ float Bs[TK][132];
    const int bh = blockIdx.z;
    const int v0 = blockIdx.x * 128, w0 = blockIdx.y * 128;
    const int tid = threadIdx.x;
    const int tx = tid & 15, ty = tid >> 4;
    u64 acc2[4][8];
    #pragma unroll
    for (int p = 0; p < 4; p++)
        #pragma unroll
        for (int j = 0; j < 8; j++) acc2[p][j] = 0ULL;

    for (int ck = 0; ck < Cc; ck += TK) {
        #pragma unroll
        for (int r = 0; r < 2; r++) {
            int f = tid + r*256;
            int k = f >> 5, c4 = (f & 31) * 4;
            *(float4*)&As[k][c4] = *(const float4*)&g_Q[0][bh][ck+k][w0+c4];
            *(float4*)&Bs[k][c4] = *(const float4*)&g_Q[1][bh][ck+k][v0+c4];
        }
        __syncthreads();
        #pragma unroll
        for (int k = 0; k < TK; k++) {
            ulonglong2 aA = *(const ulonglong2*)&As[k][ty*4];
            ulonglong2 aB = *(const ulonglong2*)&As[k][64 + ty*4];
            u64 A2[4] = {aA.x, aA.y, aB.x, aB.y};
            float4 b0 = *(const float4*)&Bs[k][tx*4];
            float4 b1 = *(const float4*)&Bs[k][64 + tx*4];
            u64 Bd[8] = {dup2f(b0.x), dup2f(b0.y), dup2f(b0.z), dup2f(b0.w),
                         dup2f(b1.x), dup2f(b1.y), dup2f(b1.z), dup2f(b1.w)};
            #pragma unroll
            for (int p = 0; p < 4; p++)
                #pragma unroll
                for (int j = 0; j < 8; j++) fma2(acc2[p][j], A2[p], Bd[j]);
        }
        __syncthreads();
    }
    const float s = 0.125f;
    #pragma unroll
    for (int p = 0; p < 4; p++) {
        int wlo = w0 + ((p < 2) ? (ty*4 + 2*p) : (64 + ty*4 + 2*(p-2)));
        float2 f[8];
        #pragma unroll
        for (int j = 0; j < 8; j++) f[j] = up2(acc2[p][j]);
        *(float4*)&g_A[bh][wlo][v0 + tx*4] = make_float4(f[0].x*s, f[1].x*s, f[2].x*s, f[3].x*s);
        *(float4*)&g_A[bh][wlo][v0 + 64 + tx*4] = make_float4(f[4].x*s, f[5].x*s, f[6].x*s, f[7].x*s);
        *(float4*)&g_A[bh][wlo+1][v0 + tx*4] = make_float4(f[0].y*s, f[1].y*s, f[2].y*s, f[3].y*s);
        *(float4*)&g_A[bh][wlo+1][v0 + 64 + tx*4] = make_float4(f[4].y*s, f[5].y*s, f[6].y*s, f[7].y*s);
    }
}

// ================= K3a: row stats (unchanged) =================
__global__ void k3a_rowstats()
{
    const int bh = blockIdx.y;
    const int w = blockIdx.x*8 + (threadIdx.x >> 5);
    const int lane = threadIdx.x & 31;
    const float* __restrict__ row = g_A[bh][w];
    float m = -1e30f;
    for (int v = lane; v < Ww; v += 32) m = fmaxf(m, row[v]);
    #pragma unroll
    for (int o = 16; o; o >>= 1) m = fmaxf(m, __shfl_xor_sync(0xffffffffu, m, o));
    float s = 0.f;
    for (int v = lane; v < Ww; v += 32) s += __expf(row[v] - m);
    #pragma unroll
    for (int o = 16; o; o >>= 1) s += __shfl_xor_sync(0xffffffffu, s, o);
    if (!lane) { g_rmax[bh][w] = m; g_rinv[bh][w] = 1.f/s; }
}

// ================= K3b: col stats (unchanged) =================
__global__ void k3b_colstats()
{
    __shared__ float redm[8][32], reds[8][32], redms[8][32];
    const int bh = blockIdx.y;
    const int tid = threadIdx.x;
    const int lane = tid & 31, g = tid >> 5;
    const int v = blockIdx.x*32 + lane;

    float m = -1e30f;
    for (int w = g; w < Ww; w += 8) m = fmaxf(m, g_A[bh][w][v]);
    redm[g][lane] = m;
    __syncthreads();
    if (g == 0) {
        for (int k = 1; k < 8; k++) m = fmaxf(m, redm[k][lane]);
        redm[0][lane] = m;
    }
    __syncthreads();
    m = redm[0][lane];

    float s = 0.f, ms = 0.f;
    for (int w = g; w < Ww; w += 8) {
        float a = g_A[bh][w][v];
        s  += __expf(a - m);
        ms += __expf(a - g_rmax[bh][w]) * g_rinv[bh][w];
    }
    reds[g][lane] = s; redms[g][lane] = ms;
    __syncthreads();
    if (g == 0) {
        for (int k = 1; k < 8; k++) { s += reds[k][lane]; ms += redms[k][lane]; }
        g_cmax[bh][v] = m;
        g_cinv[bh][v] = 1.f/s;
        g_ms_r2l[bh][v] = ms;
    }
}

// ================= K4: write M matrices (unchanged) =================
__global__ void k4_writeM()
{
    const int bh = blockIdx.y;
    const int u = blockIdx.x*8 + (threadIdx.x >> 5);
    const int lane = threadIdx.x & 31;
    const float rm = g_rmax[bh][u], ri = g_rinv[bh][u];
    const float* __restrict__ row = g_A[bh][u];
    float msum = 0.f;
    for (int v = lane; v < Ww; v += 32) {
        float a = row[v];
        g_Mr2l[bh][u][v] = __expf(a - rm) * ri;
        float m2 = __expf(a - g_cmax[bh][v]) * g_cinv[bh][v];
        g_MLT[bh][u][v] = m2;
        msum += m2;
    }
    #pragma unroll
    for (int o = 16; o; o >>= 1) msum += __shfl_xor_sync(0xffffffffu, msum, o);
    if (!lane) g_ms_l2r[bh][u] = msum;
}

// ================= K5: cycle loss GEMMs, FFMA2 =================
__global__ void __launch_bounds__(256) k5_cycle()
{
    __shared__ float As[TK][132];
    __shared__ float Bs[TK][132];
    __shared__ float red[256];
    const int z = blockIdx.z;
    const int term = z & 1, bh = z >> 1;
    const int u0 = blockIdx.x*128, w0 = blockIdx.y*128;
    const int tid = threadIdx.x;
    const int tx = tid & 15, ty = tid >> 4;
    u64 acc2[4][8];
    #pragma unroll
    for (int p = 0; p < 4; p++)
        #pragma unroll
        for (int j = 0; j < 8; j++) acc2[p][j] = 0ULL;

    for (int vk = 0; vk < Ww; vk += TK) {
        if (term == 0) {
            #pragma unroll
            for (int r = 0; r < 2; r++) {
                int idx = tid + r*256;
                int i = idx >> 2, j = (idx & 3)*4;
                float4 va = *(const float4*)&g_Mr2l[bh][w0+i][vk+j];
                As[j+0][i] = va.x; As[j+1][i] = va.y; As[j+2][i] = va.z; As[j+3][i] = va.w;
                float4 vb = *(const float4*)&g_MLT[bh][u0+i][vk+j];
                Bs[j+0][i] = vb.x; Bs[j+1][i] = vb.y; Bs[j+2][i] = vb.z; Bs[j+3][i] = vb.w;
            }
        } else {
            #pragma unroll
            for (int r = 0; r < 2; r++) {
                int idx = tid + r*256;
                int k = idx >> 5, wq = (idx & 31)*4;
                *(float4*)&As[k][wq] = *(const float4*)&g_MLT[bh][vk+k][w0+wq];
                *(float4*)&Bs[k][wq] = *(const float4*)&g_Mr2l[bh][vk+k][u0+wq];
            }
        }
        __syncthreads();
        #pragma unroll
        for (int k = 0; k < TK; k++) {
            ulonglong2 aA = *(const ulonglong2*)&As[k][ty*4];
            ulonglong2 aB = *(const ulonglong2*)&As[k][64 + ty*4];
            u64 A2[4] = {aA.x, aA.y, aB.x, aB.y};
            float4 b0 = *(const float4*)&Bs[k][tx*4];
            float4 b1 = *(const float4*)&Bs[k][64 + tx*4];
            u64 Bd[8] = {dup2f(b0.x), dup2f(b0.y), dup2f(b0.z), dup2f(b0.w),
                         dup2f(b1.x), dup2f(b1.y), dup2f(b1.z), dup2f(b1.w)};
            #pragma unroll
            for (int p = 0; p < 4; p++)
                #pragma unroll
                for (int j = 0; j < 8; j++) fma2(acc2[p][j], A2[p], Bd[j]);
        }
        __syncthreads();
    }

    const float* msrow = (term == 0) ? g_ms_l2r[bh] : g_ms_r2l[bh];
    float lsum = 0.f;
    #pragma unroll
    for (int j = 0; j < 8; j++) {
        int u = u0 + ((j < 4) ? (tx*4 + j) : (64 + tx*4 + (j - 4)));
        float mk = (msrow[u] > 0.1f) ? 1.f : 0.f;
        #pragma unroll
        for (int p = 0; p < 4; p++) {
            int wlo = w0 + ((p < 2) ? (ty*4 + 2*p) : (64 + ty*4 + 2*(p-2)));
            float2 f = up2(acc2[p][j]);
            lsum += mk * (fabsf(f.x - ((wlo   == u) ? 1.f : 0.f))
                        + fabsf(f.y - ((wlo+1 == u) ? 1.f : 0.f)));
        }
    }
    red[tid] = lsum; __syncthreads();
    for (int s = 128; s; s >>= 1) { if (tid < s) red[tid] += red[tid+s]; __syncthreads(); }
    if (!tid) g_p_cyc[z*9 + blockIdx.y*3 + blockIdx.x] = red[0];
}

// ================= K6: outputs, FFMA2 =================
__global__ void __launch_bounds__(256) k6_fout(const float* __restrict__ x,
                                               const float* __restrict__ bg,
                                               float* __restrict__ out, int side)
{
    __shared__ float As[TK][132];
    __shared__ float Vs[TK][68];
    const int bh = blockIdx.y;
    const int b = bh / Hh, h = bh % Hh;
    const int w0 = blockIdx.x * 128;
    const int tid = threadIdx.x;
    const int tx = tid & 15, ty = tid >> 4;
    const int vside = (side == 0) ? 1 : 0;
    u64 acc2[4][4];
    #pragma unroll
    for (int p = 0; p < 4; p++)
        #pragma unroll
        for (int j = 0; j < 4; j++) acc2[p][j] = 0ULL;

    for (int vk = 0; vk < Ww; vk += TK) {
        if (side == 0) {
            #pragma unroll
            for (int r = 0; r < 2; r++) {
                int idx = tid + r*256;
                int i = idx >> 2, j = (idx & 3)*4;
                float4 va = *(const float4*)&g_Mr2l[bh][w0+i][vk+j];
                As[j+0][i] = va.x; As[j+1][i] = va.y; As[j+2][i] = va.z; As[j+3][i] = va.w;
            }
        } else {
            #pragma unroll
            for (int r = 0; r < 2; r++) {
                int idx = tid + r*256;
                int k = idx >> 5, wq = (idx & 31)*4;
                *(float4*)&As[k][wq] = *(const float4*)&g_MLT[bh][vk+k][w0+wq];
            }
        }
        {
            int k = tid >> 4, c4 = (tid & 15)*4;
            *(float4*)&Vs[k][c4] = *(const float4*)&g_V[vside][bh][vk+k][c4];
        }
        __syncthreads();
        #pragma unroll
        for (int k = 0; k < TK; k++) {
            ulonglong2 aA = *(const ulonglong2*)&As[k][ty*4];
            ulonglong2 aB = *(const ulonglong2*)&As[k][64 + ty*4];
            u64 A2[4] = {aA.x, aA.y, aB.x, aB.y};
            float4 vv = *(const float4*)&Vs[k][tx*4];
            u64 Bd[4] = {dup2f(vv.x), dup2f(vv.y), dup2f(vv.z), dup2f(vv.w)};
            #pragma unroll
            for (int p = 0; p < 4; p++)
                #pragma unroll
                for (int j = 0; j < 4; j++) fma2(acc2[p][j], A2[p], Bd[j]);
        }
        __syncthreads();
    }
    #pragma unroll
    for (int j = 0; j < 4; j++) {
        int c = tx*4 + j;
        float bgc = bg[c];
        #pragma unroll
        for (int p = 0; p < 4; p++) {
            int wlo = w0 + ((p < 2) ? (ty*4 + 2*p) : (64 + ty*4 + 2*(p-2)));
            float2 f = up2(acc2[p][j]);
            long gi = (((long)b*Cc + c)*Hh + h)*Ww + wlo;
            out[gi]   = x[gi]   + bgc*f.x;
            out[gi+1] = x[gi+1] + bgc*f.y;
        }
    }
}

// ================= K7a (unchanged) =================
__global__ void k7a_photo1(const float* __restrict__ LRl, const float* __restrict__ LRr)
{
    __shared__ float lr[3][Ww];
    __shared__ float r8[8];
    const int bh = blockIdx.y;
    const int b = bh / Hh, h = bh % Hh;
    const int w = blockIdx.x*8 + (threadIdx.x >> 5);
    const int lane = threadIdx.x & 31;
    for (int idx = threadIdx.x; idx < 3*Ww; idx += 256) {
        int ch = idx / Ww, v = idx % Ww;
        lr[ch][v] = LRr[(((long)b*3 + ch)*Hh + h)*Ww + v];
    }
    __syncthreads();
    float a0 = 0.f, a1 = 0.f, a2 = 0.f;
    const float* __restrict__ mrow = g_Mr2l[bh][w];
    for (int v = lane; v < Ww; v += 32) {
        float m = mrow[v];
        a0 += m*lr[0][v]; a1 += m*lr[1][v]; a2 += m*lr[2][v];
    }
    #pragma unroll
    for (int o = 16; o; o >>= 1) {
        a0 += __shfl_xor_sync(0xffffffffu, a0, o);
        a1 += __shfl_xor_sync(0xffffffffu, a1, o);
        a2 += __shfl_xor_sync(0xffffffffu, a2, o);
    }
    if (!lane) {
        float mk = (g_ms_l2r[bh][w] > 0.1f) ? 1.f : 0.f;
        long base = (((long)b*3)*Hh + h)*Ww + w;
        float part = mk * (fabsf(LRl[base] - a0)
                         + fabsf(LRl[base + (long)Hh*Ww] - a1)
                         + fabsf(LRl[base + 2L*Hh*Ww] - a2));
        r8[threadIdx.x >> 5] = part;
    }
    __syncthreads();
    if (threadIdx.x == 0) {
        float s = 0.f;
        for (int k = 0; k < 8; k++) s += r8[k];
        g_p_ph1[bh*48 + blockIdx.x] = s;
    }
}

// ================= K7b (unchanged) =================
__global__ void k7b_photo2(const float* __restrict__ LRl, const float* __restrict__ LRr)
{
    __shared__ float la[3][Ww], lb[3][Ww];
    __shared__ float red[128];
    const int bh = blockIdx.x;
    const int b = bh / Hh, h = bh % Hh;
    const int tid = threadIdx.x;
    for (int idx = tid; idx < 3*Ww; idx += 128) {
        int ch = idx / Ww, w = idx % Ww;
        long gi = (((long)b*3 + ch)*Hh + h)*Ww + w;
        la[ch][w] = LRl[gi];
        lb[ch][w] = LRr[gi];
    }
    __syncthreads();
    float acc[3][3] = {};
    for (int v = 0; v < Ww; v++) {
        const float* __restrict__ mr = g_MLT[bh][v];
        float l0 = la[0][v], l1 = la[1][v], l2 = la[2][v];
        #pragma unroll
        for (int s = 0; s < 3; s++) {
            float m = mr[tid + s*128];
            acc[s][0] += m*l0; acc[s][1] += m*l1; acc[s][2] += m*l2;
        }
    }
    float part = 0.f;
    #pragma unroll
    for (int s = 0; s < 3; s++) {
        int w = tid + s*128;
        float mk = (g_ms_r2l[bh][w] > 0.1f) ? 1.f : 0.f;
        part += mk * (fabsf(lb[0][w] - acc[s][0])
                    + fabsf(lb[1][w] - acc[s][1])
                    + fabsf(lb[2][w] - acc[s][2]));
    }
    red[tid] = part; __syncthreads();
    for (int s = 64; s; s >>= 1) { if (tid < s) red[tid] += red[tid+s]; __syncthreads(); }
    if (!tid) g_p_ph2[bh] = red[0];
}

// ================= K8 (unchanged) =================
__global__ void k8_smooth()
{
    __shared__ float redh[256], redw[256];
    const int mat = blockIdx.z, bh = blockIdx.y, w0 = blockIdx.x*16;
    const int h = bh % Hh;
    const float* __restrict__ M = mat ? &g_MLT[0][0][0] : &g_Mr2l[0][0][0];
    const int tid = threadIdx.x;
    float sh = 0.f, sw = 0.f;
    for (int idx = tid; idx < 16*Ww; idx += 256) {
        int w = w0 + idx / Ww, v = idx % Ww;
        long base = ((long)bh*Ww + w)*Ww + v;
        float m = M[base];
        if (h < Hh - 1) sh += fabsf(m - M[base + (long)Ww*Ww]);
        if (w < Ww - 1 && v < Ww - 1) sw += fabsf(m - M[base + Ww + 1]);
    }
    redh[tid] = sh; redw[tid] = sw; __syncthreads();
    for (int s = 128; s; s >>= 1) {
        if (tid < s) { redh[tid] += redh[tid+s]; redw[tid] += redw[tid+s]; }
        __syncthreads();
    }
    if (!tid) {
        int slot = (mat*BHn + bh)*24 + blockIdx.x;
        g_p_smh[slot] = redh[0];
        g_p_smw[slot] = redw[0];
    }
}

// ================= K9 (unchanged) =================
__global__ void k9_final(const float* __restrict__ loss_in, float* __restrict__ out_loss)
{
    __shared__ double red[256];
    const int tid = threadIdx.x;
    double acc[4] = {0.0, 0.0, 0.0, 0.0};
    for (int i = tid; i < NP_CYC; i += 256) acc[0] += (double)g_p_cyc[i];
    for (int i = tid; i < NP_PH1; i += 256) acc[1] += (double)g_p_ph1[i];
    for (int i = tid; i < NP_PH2; i += 256) acc[1] += (double)g_p_ph2[i];
    for (int i = tid; i < NP_SM;  i += 256) acc[2] += (double)g_p_smh[i];
    for (int i = tid; i < NP_SM;  i += 256) acc[3] += (double)g_p_smw[i];
    double tot[4];
    for (int a = 0; a < 4; a++) {
        red[tid] = acc[a]; __syncthreads();
        for (int s = 128; s; s >>= 1) { if (tid < s) red[tid] += red[tid+s]; __syncthreads(); }
        tot[a] = red[0]; __syncthreads();
    }
    if (!tid) {
        double lc = tot[0] / ((double)Bz*Hh*Ww*Ww);
        double lp = tot[1] / ((double)Bz*3*Hh*Ww);
        double lh = tot[2] / ((double)Bz*(Hh-1)*Ww*Ww);
        double lw = tot[3] / ((double)Bz*Hh*(Ww-1)*(Ww-1));
        out_loss[0] = (float)((double)loss_in[0] + 0.0025*(lp + 0.1*(lw + lh) + lc));
    }
}

extern "C" void kernel_launch(void* const* d_in, const int* in_sizes, int n_in,
                              void* d_out, int out_size)
{
    (void)in_sizes; (void)n_in; (void)out_size;
    const float* x_l   = (const float*)d_in[0];
    const float* x_r   = (const float*)d_in[1];
    const float* LRl   = (const float*)d_in[2];
    const float* LRr   = (const float*)d_in[3];
    const float* lossi = (const float*)d_in[4];
    const float* nlw = (const float*)d_in[5];
    const float* nlb = (const float*)d_in[6];
    const float* nrw = (const float*)d_in[7];
    const float* nrb = (const float*)d_in[8];
    const float* lp1w = (const float*)d_in[9];
    const float* lp1b = (const float*)d_in[10];
    const float* rp1w = (const float*)d_in[11];
    const float* rp1b = (const float*)d_in[12];
    const float* lp2w = (const float*)d_in[13];
    const float* lp2b = (const float*)d_in[14];
    const float* rp2w = (const float*)d_in[15];
    const float* rp2b = (const float*)d_in[16];
    const float* beta  = (const float*)d_in[17];
    const float* gamma = (const float*)d_in[18];

    float* out = (float*)d_out;
    float* out_xl   = out;
    float* out_xr   = out + NX;
    float* out_lrl  = out + 2L*NX;
    float* out_lrr  = out + 2L*NX + NLR;
    float* out_loss = out + 2L*NX + 2L*NLR;

    const size_t smem1 = (size_t)(Cc*PIX + 2*Cc*Cc + 2*Cc + 2*PIX) * sizeof(float);
    cudaFuncSetAttribute(k1_lnproj, cudaFuncAttributeMaxDynamicSharedMemorySize, (int)smem1);

    k1_lnproj<<<dim3(2, BHn), 256, smem1>>>(x_l, nlw, nlb, lp1w, lp1b, lp2w, lp2b, 0);
    k1_lnproj<<<dim3(2, BHn), 256, smem1>>>(x_r, nrw, nrb, rp1w, rp1b, rp2w, rp2b, 1);
    k2_attn<<<dim3(3, 3, BHn), 256>>>();
    k3a_rowstats<<<dim3(48, BHn), 256>>>();
    k3b_colstats<<<dim3(12, BHn), 256>>>();
    k4_writeM<<<dim3(48, BHn), 256>>>();
    k5_cycle<<<dim3(3, 3, BHn*2), 256>>>();
    k6_fout<<<dim3(3, BHn), 256>>>(x_l, beta, out_xl, 0);
    k6_fout<<<dim3(3, BHn), 256>>>(x_r, gamma, out_xr, 1);
    k7a_photo1<<<dim3(48, BHn), 256>>>(LRl, LRr);
    k7b_photo2<<<BHn, 128>>>(LRl, LRr);
    k8_smooth<<<dim3(24, BHn, 2), 256>>>();
    cudaMemcpyAsync(out_lrl, LRl, (size_t)NLR*sizeof(float), cudaMemcpyDeviceToDevice, 0);
    cudaMemcpyAsync(out_lrr, LRr, (size_t)NLR*sizeof(float), cudaMemcpyDeviceToDevice, 0);
    k9_final<<<1, 256>>>(lossi, out_loss);
}

// round 6
// speedup vs baseline: 1.6330x; 1.4467x over previous
#include <cuda_runtime.h>
#include <cuda_bf16.h>
#include <math.h>

#define Bz 4
#define Cc 64
#define Hh 96
#define Ww 384
#define BHn (Bz*Hh)
#define NX (Bz*Cc*Hh*Ww)
#define NLR (Bz*3*Hh*Ww)
#define EPS 1e-6f

typedef unsigned long long u64;
typedef unsigned int u32;
__device__ __forceinline__ u64 dup2f(float x) {
    u64 r; asm("mov.b64 %0, {%1, %1};" : "=l"(r) : "f"(x)); return r;
}
__device__ __forceinline__ void fma2(u64 &d, u64 a, u64 b) {
    asm("fma.rn.f32x2 %0, %1, %2, %0;" : "+l"(d) : "l"(a), "l"(b));
}
__device__ __forceinline__ float2 up2(u64 v) {
    float2 r; asm("mov.b64 {%0, %1}, %2;" : "=f"(r.x), "=f"(r.y) : "l"(v)); return r;
}
__device__ __forceinline__ u32 smem_u32(const void* p) {
    u32 a; asm("{ .reg .u64 t; cvta.to.shared.u64 t, %1; cvt.u32.u64 %0, t; }" : "=r"(a) : "l"(p));
    return a;
}

__device__ __align__(16) float g_Q[2][BHn][Cc][Ww];
__device__ __align__(16) float g_V[2][BHn][Ww][Cc];
__device__ __align__(16) float g_A[BHn][Ww][Ww];
__device__ __align__(16) float g_Mr2l[BHn][Ww][Ww];
__device__ __align__(16) float g_MLT[BHn][Ww][Ww];
__device__ __align__(16) __nv_bfloat16 b_Mr2l[BHn][Ww][Ww];
__device__ __align__(16) __nv_bfloat16 b_MLT[BHn][Ww][Ww];
__device__ __align__(16) __nv_bfloat16 b_Mr2lT[BHn][Ww][Ww];
__device__ __align__(16) __nv_bfloat16 b_MLTT[BHn][Ww][Ww];
__device__ float g_rmax[BHn][Ww];
__device__ float g_rinv[BHn][Ww];
__device__ float g_cmax[BHn][Ww];
__device__ float g_cinv[BHn][Ww];
__device__ float g_ms_r2l[BHn][Ww];
__device__ float g_ms_l2r[BHn][Ww];

#define NP_CYC (2*BHn*9)
#define NP_PH1 (48*BHn)
#define NP_PH2 (BHn)
#define NP_SM  (2*BHn*24)
__device__ float g_p_cyc[NP_CYC];
__device__ float g_p_ph1[NP_PH1];
__device__ float g_p_ph2[NP_PH2];
__device__ float g_p_smh[NP_SM];
__device__ float g_p_smw[NP_SM];

// ================= K1: LN + both 1x1 projections =================
#define PIX 192
__global__ void k1_lnproj(const float* __restrict__ x,
                          const float* __restrict__ nw, const float* __restrict__ nb,
                          const float* __restrict__ p1, const float* __restrict__ b1,
                          const float* __restrict__ p2, const float* __restrict__ b2,
                          int side)
{
    extern __shared__ float sm[];
    float* xs   = sm;
    float* w1   = xs + Cc*PIX;
    float* w2   = w1 + Cc*Cc;
    float* s1   = w2 + Cc*Cc;
    float* t1   = s1 + Cc;
    float* mval = t1 + Cc;
    float* rval = mval + PIX;

    const int bh = blockIdx.y;
    const int b = bh / Hh, h = bh % Hh;
    const int w0 = blockIdx.x * PIX;
    const int tid = threadIdx.x;

    for (int idx = tid; idx < Cc*Cc; idx += 256) {
        int c = idx & 63;
        w1[idx] = p1[idx] * nw[c];
        w2[idx] = p2[idx];
    }
    for (int idx = tid; idx < Cc*PIX; idx += 256) {
        int c = idx / PIX, p = idx % PIX;
        xs[idx] = x[(((long)b*Cc + c)*Hh + h)*Ww + w0 + p];
    }
    __syncthreads();

    for (int o = tid; o < Cc; o += 256) {
        float s = 0.f, t = b1[o];
        for (int c = 0; c < Cc; c++) { s += w1[o*Cc + c]; t += p1[o*Cc + c]*nb[c]; }
        s1[o] = s; t1[o] = t;
    }
    for (int p = tid; p < PIX; p += 256) {
        float s = 0.f, q = 0.f;
        for (int c = 0; c < Cc; c++) { float v = xs[c*PIX + p]; s += v; q += v*v; }
        float mu = s * (1.f/Cc);
        float var = q*(1.f/Cc) - mu*mu;
        float r = rsqrtf(var + EPS);
        rval[p] = r; mval[p] = -r*mu;
    }
    __syncthreads();

    const int tx = tid & 15, ty = tid >> 4;
    float acc[4][12];

    #pragma unroll
    for (int i = 0; i < 4; i++)
        #pragma unroll
        for (int j = 0; j < 12; j++) acc[i][j] = 0.f;
    for (int c = 0; c < Cc; c++) {
        float a0 = w1[(ty*4+0)*Cc+c], a1 = w1[(ty*4+1)*Cc+c];
        float a2 = w1[(ty*4+2)*Cc+c], a3 = w1[(ty*4+3)*Cc+c];
        #pragma unroll
        for (int j = 0; j < 12; j++) {
            float xv = xs[c*PIX + tx + 16*j];
            acc[0][j] += a0*xv; acc[1][j] += a1*xv; acc[2][j] += a2*xv; acc[3][j] += a3*xv;
        }
    }
    #pragma unroll
    for (int i = 0; i < 4; i++) {
        int o = ty*4 + i;
        float so = s1[o], to = t1[o];
        #pragma unroll
        for (int j = 0; j < 12; j++) {
            int p = tx + 16*j;
            g_Q[side][bh][o][w0+p] = rval[p]*acc[i][j] + mval[p]*so + to;
        }
    }

    #pragma unroll
    for (int i = 0; i < 4; i++)
        #pragma unroll
        for (int j = 0; j < 12; j++) acc[i][j] = 0.f;
    for (int c = 0; c < Cc; c++) {
        float a0 = w2[(ty*4+0)*Cc+c], a1 = w2[(ty*4+1)*Cc+c];
        float a2 = w2[(ty*4+2)*Cc+c], a3 = w2[(ty*4+3)*Cc+c];
        #pragma unroll
        for (int j = 0; j < 12; j++) {
            float xv = xs[c*PIX + tx + 16*j];
            acc[0][j] += a0*xv; acc[1][j] += a1*xv; acc[2][j] += a2*xv; acc[3][j] += a3*xv;
        }
    }
    float bo0 = b2[ty*4], bo1 = b2[ty*4+1], bo2 = b2[ty*4+2], bo3 = b2[ty*4+3];
    #pragma unroll
    for (int j = 0; j < 12; j++) {
        int p = tx + 16*j;
        float4 vv = make_float4(acc[0][j]+bo0, acc[1][j]+bo1, acc[2][j]+bo2, acc[3][j]+bo3);
        *(float4*)&g_V[side][bh][w0+p][ty*4] = vv;
    }
}

// ================= K2: attention logits, FFMA2 =================
#define TK 16
__global__ void __launch_bounds__(256) k2_attn()
{
    __shared__ float As[TK][132];
    __shared__ float Bs[TK][132];
    const int bh = blockIdx.z;
    const int v0 = blockIdx.x * 128, w0 = blockIdx.y * 128;
    const int tid = threadIdx.x;
    const int tx = tid & 15, ty = tid >> 4;
    u64 acc2[4][8];
    #pragma unroll
    for (int p = 0; p < 4; p++)
        #pragma unroll
        for (int j = 0; j < 8; j++) acc2[p][j] = 0ULL;

    for (int ck = 0; ck < Cc; ck += TK) {
        #pragma unroll
        for (int r = 0; r < 2; r++) {
            int f = tid + r*256;
            int k = f >> 5, c4 = (f & 31) * 4;
            *(float4*)&As[k][c4] = *(const float4*)&g_Q[0][bh][ck+k][w0+c4];
            *(float4*)&Bs[k][c4] = *(const float4*)&g_Q[1][bh][ck+k][v0+c4];
        }
        __syncthreads();
        #pragma unroll
        for (int k = 0; k < TK; k++) {
            ulonglong2 aA = *(const ulonglong2*)&As[k][ty*4];
            ulonglong2 aB = *(const ulonglong2*)&As[k][64 + ty*4];
            u64 A2[4] = {aA.x, aA.y, aB.x, aB.y};
            float4 b0 = *(const float4*)&Bs[k][tx*4];
            float4 b1 = *(const float4*)&Bs[k][64 + tx*4];
            u64 Bd[8] = {dup2f(b0.x), dup2f(b0.y), dup2f(b0.z), dup2f(b0.w),
                         dup2f(b1.x), dup2f(b1.y), dup2f(b1.z), dup2f(b1.w)};
            #pragma unroll
            for (int p = 0; p < 4; p++)
                #pragma unroll
                for (int j = 0; j < 8; j++) fma2(acc2[p][j], A2[p], Bd[j]);
        }
        __syncthreads();
    }
    const float s = 0.125f;
    #pragma unroll
    for (int p = 0; p < 4; p++) {
        int wlo = w0 + ((p < 2) ? (ty*4 + 2*p) : (64 + ty*4 + 2*(p-2)));
        float2 f[8];
        #pragma unroll
        for (int j = 0; j < 8; j++) f[j] = up2(acc2[p][j]);
        *(float4*)&g_A[bh][wlo][v0 + tx*4] = make_float4(f[0].x*s, f[1].x*s, f[2].x*s, f[3].x*s);
        *(float4*)&g_A[bh][wlo][v0 + 64 + tx*4] = make_float4(f[4].x*s, f[5].x*s, f[6].x*s, f[7].x*s);
        *(float4*)&g_A[bh][wlo+1][v0 + tx*4] = make_float4(f[0].y*s, f[1].y*s, f[2].y*s, f[3].y*s);
        *(float4*)&g_A[bh][wlo+1][v0 + 64 + tx*4] = make_float4(f[4].y*s, f[5].y*s, f[6].y*s, f[7].y*s);
    }
}

// ================= K3a: row stats =================
__global__ void k3a_rowstats()
{
    const int bh = blockIdx.y;
    const int w = blockIdx.x*8 + (threadIdx.x >> 5);
    const int lane = threadIdx.x & 31;
    const float* __restrict__ row = g_A[bh][w];
    float m = -1e30f;
    for (int v = lane; v < Ww; v += 32) m = fmaxf(m, row[v]);
    #pragma unroll
    for (int o = 16; o; o >>= 1) m = fmaxf(m, __shfl_xor_sync(0xffffffffu, m, o));
    float s = 0.f;
    for (int v = lane; v < Ww; v += 32) s += __expf(row[v] - m);
    #pragma unroll
    for (int o = 16; o; o >>= 1) s += __shfl_xor_sync(0xffffffffu, s, o);
    if (!lane) { g_rmax[bh][w] = m; g_rinv[bh][w] = 1.f/s; }
}

// ================= K3b: col stats =================
__global__ void k3b_colstats()
{
    __shared__ float redm[8][32], reds[8][32], redms[8][32];
    const int bh = blockIdx.y;
    const int tid = threadIdx.x;
    const int lane = tid & 31, g = tid >> 5;
    const int v = blockIdx.x*32 + lane;

    float m = -1e30f;
    for (int w = g; w < Ww; w += 8) m = fmaxf(m, g_A[bh][w][v]);
    redm[g][lane] = m;
    __syncthreads();
    if (g == 0) {
        for (int k = 1; k < 8; k++) m = fmaxf(m, redm[k][lane]);
        redm[0][lane] = m;
    }
    __syncthreads();
    m = redm[0][lane];

    float s = 0.f, ms = 0.f;
    for (int w = g; w < Ww; w += 8) {
        float a = g_A[bh][w][v];
        s  += __expf(a - m);
        ms += __expf(a - g_rmax[bh][w]) * g_rinv[bh][w];
    }
    reds[g][lane] = s; redms[g][lane] = ms;
    __syncthreads();
    if (g == 0) {
        for (int k = 1; k < 8; k++) { s += reds[k][lane]; ms += redms[k][lane]; }
        g_cmax[bh][v] = m;
        g_cinv[bh][v] = 1.f/s;
        g_ms_r2l[bh][v] = ms;
    }
}

// ================= K4: write M matrices (fp32) =================
__global__ void k4_writeM()
{
    const int bh = blockIdx.y;
    const int u = blockIdx.x*8 + (threadIdx.x >> 5);
    const int lane = threadIdx.x & 31;
    const float rm = g_rmax[bh][u], ri = g_rinv[bh][u];
    const float* __restrict__ row = g_A[bh][u];
    float msum = 0.f;
    for (int v = lane; v < Ww; v += 32) {
        float a = row[v];
        g_Mr2l[bh][u][v] = __expf(a - rm) * ri;
        float m2 = __expf(a - g_cmax[bh][v]) * g_cinv[bh][v];
        g_MLT[bh][u][v] = m2;
        msum += m2;
    }
    #pragma unroll
    for (int o = 16; o; o >>= 1) msum += __shfl_xor_sync(0xffffffffu, msum, o);
    if (!lane) g_ms_l2r[bh][u] = msum;
}

// ================= K4T: bf16 copies in all 4 orientations =================
__device__ __forceinline__ uint2 pack4bf(float a, float b, float c, float d) {
    __nv_bfloat162 p0 = __floats2bfloat162_rn(a, b);
    __nv_bfloat162 p1 = __floats2bfloat162_rn(c, d);
    uint2 r;
    r.x = *(u32*)&p0; r.y = *(u32*)&p1;
    return r;
}
__global__ void __launch_bounds__(256) k4t_transpose()
{
    __shared__ __align__(16) float s1[64][68];
    __shared__ __align__(16) float s2[64][68];
    const int bh = blockIdx.z;
    const int v0 = blockIdx.x*64, u0 = blockIdx.y*64;
    const int tid = threadIdx.x;
    const int tx = tid & 15, ty = tid >> 4;
    #pragma unroll
    for (int i = 0; i < 4; i++) {
        int u = u0 + ty*4 + i;
        float4 a1 = *(const float4*)&g_Mr2l[bh][u][v0 + tx*4];
        float4 a2 = *(const float4*)&g_MLT[bh][u][v0 + tx*4];
        *(uint2*)&b_Mr2l[bh][u][v0 + tx*4] = pack4bf(a1.x, a1.y, a1.z, a1.w);
        *(uint2*)&b_MLT[bh][u][v0 + tx*4]  = pack4bf(a2.x, a2.y, a2.z, a2.w);
        *(float4*)&s1[ty*4+i][tx*4] = a1;
        *(float4*)&s2[ty*4+i][tx*4] = a2;
    }
    __syncthreads();
    #pragma unroll
    for (int i = 0; i < 4; i++) {
        int vl = ty*4 + i;
        int v = v0 + vl;
        *(uint2*)&b_Mr2lT[bh][v][u0 + tx*4] =
            pack4bf(s1[tx*4+0][vl], s1[tx*4+1][vl], s1[tx*4+2][vl], s1[tx*4+3][vl]);
        *(uint2*)&b_MLTT[bh][v][u0 + tx*4] =
            pack4bf(s2[tx*4+0][vl], s2[tx*4+1][vl], s2[tx*4+2][vl], s2[tx*4+3][vl]);
    }
}

// ================= K5: cycle loss via warp MMA (bf16 HMMA) =================
#define APAD 40
__device__ __forceinline__ void ldsm4(u32& r0, u32& r1, u32& r2, u32& r3, u32 addr) {
    asm volatile("ldmatrix.sync.aligned.m8n8.x4.shared.b16 {%0,%1,%2,%3}, [%4];"
                 : "=r"(r0), "=r"(r1), "=r"(r2), "=r"(r3) : "r"(addr));
}
__device__ __forceinline__ void mma_bf16(float* c, const u32* a, u32 b0, u32 b1) {
    asm volatile("mma.sync.aligned.m16n8k16.row.col.f32.bf16.bf16.f32 "
                 "{%0,%1,%2,%3}, {%4,%5,%6,%7}, {%8,%9}, {%0,%1,%2,%3};"
                 : "+f"(c[0]), "+f"(c[1]), "+f"(c[2]), "+f"(c[3])
                 : "r"(a[0]), "r"(a[1]), "r"(a[2]), "r"(a[3]), "r"(b0), "r"(b1));
}
__global__ void __launch_bounds__(256) k5_cycle_mma()
{
    __shared__ __align__(16) __nv_bfloat16 As[128][APAD];
    __shared__ __align__(16) __nv_bfloat16 Bs[128][APAD];
    __shared__ float red[256];
    const int z = blockIdx.z, term = z & 1, bh = z >> 1;
    const int u0 = blockIdx.x*128, w0 = blockIdx.y*128;
    const int tid = threadIdx.x, wid = tid >> 5, lane = tid & 31;
    const int wm = wid >> 2, wn = wid & 3;
    const __nv_bfloat16* __restrict__ Ag = term == 0 ? &b_Mr2l[bh][w0][0] : &b_MLTT[bh][w0][0];
    const __nv_bfloat16* __restrict__ Bg = term == 0 ? &b_MLT[bh][u0][0]  : &b_Mr2lT[bh][u0][0];

    float c[4][4][4];
    #pragma unroll
    for (int mt = 0; mt < 4; mt++)
        #pragma unroll
        for (int nt = 0; nt < 4; nt++)
            #pragma unroll
            for (int i = 0; i < 4; i++) c[mt][nt][i] = 0.f;

    const u32 a_base = smem_u32(As), b_base = smem_u32(Bs);
    const u32 a_row = wm*64 + (lane & 15);
    const u32 a_coff = (lane >> 4) * 16;
    const u32 b_row = wn*32 + (lane & 7) + ((lane >> 4) << 3);
    const u32 b_coff = ((lane >> 3) & 1) * 16;

    for (int ch = 0; ch < 12; ch++) {
        #pragma unroll
        for (int p = 0; p < 2; p++) {
            int idx = tid + p*256;
            int row = idx >> 2, seg = idx & 3;
            const long go = (long)row*Ww + ch*32 + seg*8;
            uint4 va = *(const uint4*)(Ag + go);
            uint4 vb = *(const uint4*)(Bg + go);
            *(uint2*)&As[row][seg*8]     = make_uint2(va.x, va.y);
            *(uint2*)&As[row][seg*8 + 4] = make_uint2(va.z, va.w);
            *(uint2*)&Bs[row][seg*8]     = make_uint2(vb.x, vb.y);
            *(uint2*)&Bs[row][seg*8 + 4] = make_uint2(vb.z, vb.w);
        }
        __syncthreads();
        #pragma unroll
        for (int ks = 0; ks < 2; ks++) {
            const u32 kb = ks*32;
            u32 bf[2][4];
            #pragma unroll
            for (int hgrp = 0; hgrp < 2; hgrp++) {
                u32 addr = b_base + (b_row + hgrp*16)*(APAD*2) + kb + b_coff;
                ldsm4(bf[hgrp][0], bf[hgrp][1], bf[hgrp][2], bf[hgrp][3], addr);
            }
            #pragma unroll
            for (int mt = 0; mt < 4; mt++) {
                u32 a[4];
                u32 addr = a_base + (a_row + mt*16)*(APAD*2) + kb + a_coff;
                ldsm4(a[0], a[1], a[2], a[3], addr);
                #pragma unroll
                for (int nt = 0; nt < 4; nt++)
                    mma_bf16(c[mt][nt], a, bf[nt >> 1][(nt & 1)*2], bf[nt >> 1][(nt & 1)*2 + 1]);
            }
        }
        __syncthreads();
    }

    const float* __restrict__ msrow = (term == 0) ? g_ms_l2r[bh] : g_ms_r2l[bh];
    float lsum = 0.f;
    #pragma unroll
    for (int nt = 0; nt < 4; nt++) {
        #pragma unroll
        for (int jj = 0; jj < 2; jj++) {
            int u = u0 + wn*32 + nt*8 + (lane & 3)*2 + jj;
            float mk = (msrow[u] > 0.1f) ? 1.f : 0.f;
            #pragma unroll
            for (int mt = 0; mt < 4; mt++) {
                #pragma unroll
                for (int hh = 0; hh < 2; hh++) {
                    int w = w0 + wm*64 + mt*16 + (lane >> 2) + hh*8;
                    float dv = c[mt][nt][hh*2 + jj];
                    lsum += mk * fabsf(dv - ((w == u) ? 1.f : 0.f));
                }
            }
        }
    }
    red[tid] = lsum; __syncthreads();
    for (int s = 128; s; s >>= 1) { if (tid < s) red[tid] += red[tid+s]; __syncthreads(); }
    if (!tid) g_p_cyc[z*9 + blockIdx.y*3 + blockIdx.x] = red[0];
}

// ================= K6: outputs, FFMA2 =================
__global__ void __launch_bounds__(256) k6_fout(const float* __restrict__ x,
                                               const float* __restrict__ bg,
                                               float* __restrict__ out, int side)
{
    __shared__ float As[TK][132];
    __shared__ float Vs[TK][68];
    const int bh = blockIdx.y;
    const int b = bh / Hh, h = bh % Hh;
    const int w0 = blockIdx.x * 128;
    const int tid = threadIdx.x;
    const int tx = tid & 15, ty = tid >> 4;
    const int vside = (side == 0) ? 1 : 0;
    u64 acc2[4][4];
    #pragma unroll
    for (int p = 0; p < 4; p++)
        #pragma unroll
        for (int j = 0; j < 4; j++) acc2[p][j] = 0ULL;

    for (int vk = 0; vk < Ww; vk += TK) {
        if (side == 0) {
            #pragma unroll
            for (int r = 0; r < 2; r++) {
                int idx = tid + r*256;
                int i = idx >> 2, j = (idx & 3)*4;
                float4 va = *(const float4*)&g_Mr2l[bh][w0+i][vk+j];
                As[j+0][i] = va.x; As[j+1][i] = va.y; As[j+2][i] = va.z; As[j+3][i] = va.w;
            }
        } else {
            #pragma unroll
            for (int r = 0; r < 2; r++) {
                int idx = tid + r*256;
                int k = idx >> 5, wq = (idx & 31)*4;
                *(float4*)&As[k][wq] = *(const float4*)&g_MLT[bh][vk+k][w0+wq];
            }
        }
        {
            int k = tid >> 4, c4 = (tid & 15)*4;
            *(float4*)&Vs[k][c4] = *(const float4*)&g_V[vside][bh][vk+k][c4];
        }
        __syncthreads();
        #pragma unroll
        for (int k = 0; k < TK; k++) {
            ulonglong2 aA = *(const ulonglong2*)&As[k][ty*4];
            ulonglong2 aB = *(const ulonglong2*)&As[k][64 + ty*4];
            u64 A2[4] = {aA.x, aA.y, aB.x, aB.y};
            float4 vv = *(const float4*)&Vs[k][tx*4];
            u64 Bd[4] = {dup2f(vv.x), dup2f(vv.y), dup2f(vv.z), dup2f(vv.w)};
            #pragma unroll
            for (int p = 0; p < 4; p++)
                #pragma unroll
                for (int j = 0; j < 4; j++) fma2(acc2[p][j], A2[p], Bd[j]);
        }
        __syncthreads();
    }
    #pragma unroll
    for (int j = 0; j < 4; j++) {
        int c = tx*4 + j;
        float bgc = bg[c];
        #pragma unroll
        for (int p = 0; p < 4; p++) {
            int wlo = w0 + ((p < 2) ? (ty*4 + 2*p) : (64 + ty*4 + 2*(p-2)));
            float2 f = up2(acc2[p][j]);
            long gi = (((long)b*Cc + c)*Hh + h)*Ww + wlo;
            out[gi]   = x[gi]   + bgc*f.x;
            out[gi+1] = x[gi+1] + bgc*f.y;
        }
    }
}

// ================= K7a =================
__global__ void k7a_photo1(const float* __restrict__ LRl, const float* __restrict__ LRr)
{
    __shared__ float lr[3][Ww];
    __shared__ float r8[8];
    const int bh = blockIdx.y;
    const int b = bh / Hh, h = bh % Hh;
    const int w = blockIdx.x*8 + (threadIdx.x >> 5);
    const int lane = threadIdx.x & 31;
    for (int idx = threadIdx.x; idx < 3*Ww; idx += 256) {
        int ch = idx / Ww, v = idx % Ww;
        lr[ch][v] = LRr[(((long)b*3 + ch)*Hh + h)*Ww + v];
    }
    __syncthreads();
    float a0 = 0.f, a1 = 0.f, a2 = 0.f;
    const float* __restrict__ mrow = g_Mr2l[bh][w];
    for (int v = lane; v < Ww; v += 32) {
        float m = mrow[v];
        a0 += m*lr[0][v]; a1 += m*lr[1][v]; a2 += m*lr[2][v];
    }
    #pragma unroll
    for (int o = 16; o; o >>= 1) {
        a0 += __shfl_xor_sync(0xffffffffu, a0, o);
        a1 += __shfl_xor_sync(0xffffffffu, a1, o);
        a2 += __shfl_xor_sync(0xffffffffu, a2, o);
    }
    if (!lane) {
        float mk = (g_ms_l2r[bh][w] > 0.1f) ? 1.f : 0.f;
        long base = (((long)b*3)*Hh + h)*Ww + w;
        float part = mk * (fabsf(LRl[base] - a0)
                         + fabsf(LRl[base + (long)Hh*Ww] - a1)
                         + fabsf(LRl[base + 2L*Hh*Ww] - a2));
        r8[threadIdx.x >> 5] = part;
    }
    __syncthreads();
    if (threadIdx.x == 0) {
        float s = 0.f;
        for (int k = 0; k < 8; k++) s += r8[k];
        g_p_ph1[bh*48 + blockIdx.x] = s;
    }
}

// ================= K7b =================
__global__ void k7b_photo2(const float* __restrict__ LRl, const float* __restrict__ LRr)
{
    __shared__ float la[3][Ww], lb[3][Ww];
    __shared__ float red[128];
    const int bh = blockIdx.x;
    const int b = bh / Hh, h = bh % Hh;
    const int tid = threadIdx.x;
    for (int idx = tid; idx < 3*Ww; idx += 128) {
        int ch = idx / Ww, w = idx % Ww;
        long gi = (((long)b*3 + ch)*Hh + h)*Ww + w;
        la[ch][w] = LRl[gi];
        lb[ch][w] = LRr[gi];
    }
    __syncthreads();
    float acc[3][3] = {};
    for (int v = 0; v < Ww; v++) {
        const float* __restrict__ mr = g_MLT[bh][v];
        float l0 = la[0][v], l1 = la[1][v], l2 = la[2][v];
        #pragma unroll
        for (int s = 0; s < 3; s++) {
            float m = mr[tid + s*128];
            acc[s][0] += m*l0; acc[s][1] += m*l1; acc[s][2] += m*l2;
        }
    }
    float part = 0.f;
    #pragma unroll
    for (int s = 0; s < 3; s++) {
        int w = tid + s*128;
        float mk = (g_ms_r2l[bh][w] > 0.1f) ? 1.f : 0.f;
        part += mk * (fabsf(lb[0][w] - acc[s][0])
                    + fabsf(lb[1][w] - acc[s][1])
                    + fabsf(lb[2][w] - acc[s][2]));
    }
    red[tid] = part; __syncthreads();
    for (int s = 64; s; s >>= 1) { if (tid < s) red[tid] += red[tid+s]; __syncthreads(); }
    if (!tid) g_p_ph2[bh] = red[0];
}

// ================= K8 =================
__global__ void k8_smooth()
{
    __shared__ float redh[256], redw[256];
    const int mat = blockIdx.z, bh = blockIdx.y, w0 = blockIdx.x*16;
    const int h = bh % Hh;
    const float* __restrict__ M = mat ? &g_MLT[0][0][0] : &g_Mr2l[0][0][0];
    const int tid = threadIdx.x;
    float sh = 0.f, sw = 0.f;
    for (int idx = tid; idx < 16*Ww; idx += 256) {
        int w = w0 + idx / Ww, v = idx % Ww;
        long base = ((long)bh*Ww + w)*Ww + v;
        float m = M[base];
        if (h < Hh - 1) sh += fabsf(m - M[base + (long)Ww*Ww]);
        if (w < Ww - 1 && v < Ww - 1) sw += fabsf(m - M[base + Ww + 1]);
    }
    redh[tid] = sh; redw[tid] = sw; __syncthreads();
    for (int s = 128; s; s >>= 1) {
        if (tid < s) { redh[tid] += redh[tid+s]; redw[tid] += redw[tid+s]; }
        __syncthreads();
    }
    if (!tid) {
        int slot = (mat*BHn + bh)*24 + blockIdx.x;
        g_p_smh[slot] = redh[0];
        g_p_smw[slot] = redw[0];
    }
}

// ================= K9 =================
__global__ void k9_final(const float* __restrict__ loss_in, float* __restrict__ out_loss)
{
    __shared__ double red[256];
    const int tid = threadIdx.x;
    double acc[4] = {0.0, 0.0, 0.0, 0.0};
    for (int i = tid; i < NP_CYC; i += 256) acc[0] += (double)g_p_cyc[i];
    for (int i = tid; i < NP_PH1; i += 256) acc[1] += (double)g_p_ph1[i];
    for (int i = tid; i < NP_PH2; i += 256) acc[1] += (double)g_p_ph2[i];
    for (int i = tid; i < NP_SM;  i += 256) acc[2] += (double)g_p_smh[i];
    for (int i = tid; i < NP_SM;  i += 256) acc[3] += (double)g_p_smw[i];
    double tot[4];
    for (int a = 0; a < 4; a++) {
        red[tid] = acc[a]; __syncthreads();
        for (int s = 128; s; s >>= 1) { if (tid < s) red[tid] += red[tid+s]; __syncthreads(); }
        tot[a] = red[0]; __syncthreads();
    }
    if (!tid) {
        double lc = tot[0] / ((double)Bz*Hh*Ww*Ww);
        double lp = tot[1] / ((double)Bz*3*Hh*Ww);
        double lh = tot[2] / ((double)Bz*(Hh-1)*Ww*Ww);
        double lw = tot[3] / ((double)Bz*Hh*(Ww-1)*(Ww-1));
        out_loss[0] = (float)((double)loss_in[0] + 0.0025*(lp + 0.1*(lw + lh) + lc));
    }
}

extern "C" void kernel_launch(void* const* d_in, const int* in_sizes, int n_in,
                              void* d_out, int out_size)
{
    (void)in_sizes; (void)n_in; (void)out_size;
    const float* x_l   = (const float*)d_in[0];
    const float* x_r   = (const float*)d_in[1];
    const float* LRl   = (const float*)d_in[2];
    const float* LRr   = (const float*)d_in[3];
    const float* lossi = (const float*)d_in[4];
    const float* nlw = (const float*)d_in[5];
    const float* nlb = (const float*)d_in[6];
    const float* nrw = (const float*)d_in[7];
    const float* nrb = (const float*)d_in[8];
    const float* lp1w = (const float*)d_in[9];
    const float* lp1b = (const float*)d_in[10];
    const float* rp1w = (const float*)d_in[11];
    const float* rp1b = (const float*)d_in[12];
    const float* lp2w = (const float*)d_in[13];
    const float* lp2b = (const float*)d_in[14];
    const float* rp2w = (const float*)d_in[15];
    const float* rp2b = (const float*)d_in[16];
    const float* beta  = (const float*)d_in[17];
    const float* gamma = (const float*)d_in[18];

    float* out = (float*)d_out;
    float* out_xl   = out;
    float* out_xr   = out + NX;
    float* out_lrl  = out + 2L*NX;
    float* out_lrr  = out + 2L*NX + NLR;
    float* out_loss = out + 2L*NX + 2L*NLR;

    const size_t smem1 = (size_t)(Cc*PIX + 2*Cc*Cc + 2*Cc + 2*PIX) * sizeof(float);
    cudaFuncSetAttribute(k1_lnproj, cudaFuncAttributeMaxDynamicSharedMemorySize, (int)smem1);

    k1_lnproj<<<dim3(2, BHn), 256, smem1>>>(x_l, nlw, nlb, lp1w, lp1b, lp2w, lp2b, 0);
    k1_lnproj<<<dim3(2, BHn), 256, smem1>>>(x_r, nrw, nrb, rp1w, rp1b, rp2w, rp2b, 1);
    k2_attn<<<dim3(3, 3, BHn), 256>>>();
    k3a_rowstats<<<dim3(48, BHn), 256>>>();
    k3b_colstats<<<dim3(12, BHn), 256>>>();
    k4_writeM<<<dim3(48, BHn), 256>>>();
    k4t_transpose<<<dim3(6, 6, BHn), 256>>>();
    k5_cycle_mma<<<dim3(3, 3, BHn*2), 256>>>();
    k6_fout<<<dim3(3, BHn), 256>>>(x_l, beta, out_xl, 0);
    k6_fout<<<dim3(3, BHn), 256>>>(x_r, gamma, out_xr, 1);
    k7a_photo1<<<dim3(48, BHn), 256>>>(LRl, LRr);
    k7b_photo2<<<BHn, 128>>>(LRl, LRr);
    k8_smooth<<<dim3(24, BHn, 2), 256>>>();
    cudaMemcpyAsync(out_lrl, LRl, (size_t)NLR*sizeof(float), cudaMemcpyDeviceToDevice, 0);
    cudaMemcpyAsync(out_lrr, LRr, (size_t)NLR*sizeof(float), cudaMemcpyDeviceToDevice, 0);
    k9_final<<<1, 256>>>(lossi, out_loss);
}

// round 9
// speedup vs baseline: 2.0037x; 1.2270x over previous
#include <cuda_runtime.h>
#include <cuda_bf16.h>
#include <math.h>

#define Bz 4
#define Cc 64
#define Hh 96
#define Ww 384
#define BHn (Bz*Hh)
#define NX (Bz*Cc*Hh*Ww)
#define NLR (Bz*3*Hh*Ww)
#define EPS 1e-6f

typedef unsigned long long u64;
typedef unsigned int u32;
typedef unsigned short u16;
__device__ __forceinline__ u64 dup2f(float x) {
    u64 r; asm("mov.b64 %0, {%1, %1};" : "=l"(r) : "f"(x)); return r;
}
__device__ __forceinline__ void fma2(u64 &d, u64 a, u64 b) {
    asm("fma.rn.f32x2 %0, %1, %2, %0;" : "+l"(d) : "l"(a), "l"(b));
}
__device__ __forceinline__ float2 up2(u64 v) {
    float2 r; asm("mov.b64 {%0, %1}, %2;" : "=f"(r.x), "=f"(r.y) : "l"(v)); return r;
}
__device__ __forceinline__ u32 smem_u32(const void* p) {
    u32 a; asm("{ .reg .u64 t; cvta.to.shared.u64 t, %1; cvt.u32.u64 %0, t; }" : "=r"(a) : "l"(p));
    return a;
}

__device__ __align__(16) float g_Q[2][BHn][Cc][Ww];
__device__ __align__(16) float g_V[2][BHn][Ww][Cc];
__device__ __align__(16) float g_A[BHn][Ww][Ww];
__device__ __align__(16) float g_Mr2l[BHn][Ww][Ww];
__device__ __align__(16) float g_MLT[BHn][Ww][Ww];
__device__ __align__(16) __nv_bfloat16 b_Mr2l[BHn][Ww][Ww];
__device__ __align__(16) __nv_bfloat16 b_MLT[BHn][Ww][Ww];
__device__ __align__(16) __nv_bfloat16 b_Mr2lT[BHn][Ww][Ww];
__device__ __align__(16) __nv_bfloat16 b_MLTT[BHn][Ww][Ww];
__device__ __align__(16) __nv_bfloat16 b_VT[2][BHn][Cc][Ww];
__device__ __align__(16) float g_rmax[BHn][Ww];
__device__ __align__(16) float g_rinv[BHn][Ww];
__device__ __align__(16) float g_cmax[BHn][Ww];
__device__ __align__(16) float g_cinv[BHn][Ww];
__device__ __align__(16) float g_ms_r2l[BHn][Ww];
__device__ __align__(16) float g_ms_l2r[BHn][Ww];

#define NP_CYC (2*BHn*9)
#define NP_PH1 (48*BHn)
#define NP_PH2 (BHn)
#define NP_SM  (2*BHn*24)
__device__ float g_p_cyc[NP_CYC];
__device__ float g_p_ph1[NP_PH1];
__device__ float g_p_ph2[NP_PH2];
__device__ float g_p_smh[NP_SM];
__device__ float g_p_smw[NP_SM];

// ================= K1: LN + both 1x1 projections (+ bf16 V^T) =================
#define PIX 192
__global__ void k1_lnproj(const float* __restrict__ x,
                          const float* __restrict__ nw, const float* __restrict__ nb,
                          const float* __restrict__ p1, const float* __restrict__ b1,
                          const float* __restrict__ p2, const float* __restrict__ b2,
                          int side)
{
    extern __shared__ float sm[];
    float* xs   = sm;
    float* w1   = xs + Cc*PIX;
    float* w2   = w1 + Cc*Cc;
    float* s1   = w2 + Cc*Cc;
    float* t1   = s1 + Cc;
    float* mval = t1 + Cc;
    float* rval = mval + PIX;

    const int bh = blockIdx.y;
    const int b = bh / Hh, h = bh % Hh;
    const int w0 = blockIdx.x * PIX;
    const int tid = threadIdx.x;

    for (int idx = tid; idx < Cc*Cc; idx += 256) {
        int c = idx & 63;
        w1[idx] = p1[idx] * nw[c];
        w2[idx] = p2[idx];
    }
    for (int idx = tid; idx < Cc*PIX; idx += 256) {
        int c = idx / PIX, p = idx % PIX;
        xs[idx] = x[(((long)b*Cc + c)*Hh + h)*Ww + w0 + p];
    }
    __syncthreads();

    for (int o = tid; o < Cc; o += 256) {
        float s = 0.f, t = b1[o];
        for (int c = 0; c < Cc; c++) { s += w1[o*Cc + c]; t += p1[o*Cc + c]*nb[c]; }
        s1[o] = s; t1[o] = t;
    }
    for (int p = tid; p < PIX; p += 256) {
        float s = 0.f, q = 0.f;
        for (int c = 0; c < Cc; c++) { float v = xs[c*PIX + p]; s += v; q += v*v; }
        float mu = s * (1.f/Cc);
        float var = q*(1.f/Cc) - mu*mu;
        float r = rsqrtf(var + EPS);
        rval[p] = r; mval[p] = -r*mu;
    }
    __syncthreads();

    const int tx = tid & 15, ty = tid >> 4;
    float acc[4][12];

    #pragma unroll
    for (int i = 0; i < 4; i++)
        #pragma unroll
        for (int j = 0; j < 12; j++) acc[i][j] = 0.f;
    for (int c = 0; c < Cc; c++) {
        float a0 = w1[(ty*4+0)*Cc+c], a1 = w1[(ty*4+1)*Cc+c];
        float a2 = w1[(ty*4+2)*Cc+c], a3 = w1[(ty*4+3)*Cc+c];
        #pragma unroll
        for (int j = 0; j < 12; j++) {
            float xv = xs[c*PIX + tx + 16*j];
            acc[0][j] += a0*xv; acc[1][j] += a1*xv; acc[2][j] += a2*xv; acc[3][j] += a3*xv;
        }
    }
    #pragma unroll
    for (int i = 0; i < 4; i++) {
        int o = ty*4 + i;
        float so = s1[o], to = t1[o];
        #pragma unroll
        for (int j = 0; j < 12; j++) {
            int p = tx + 16*j;
            g_Q[side][bh][o][w0+p] = rval[p]*acc[i][j] + mval[p]*so + to;
        }
    }

    #pragma unroll
    for (int i = 0; i < 4; i++)
        #pragma unroll
        for (int j = 0; j < 12; j++) acc[i][j] = 0.f;
    for (int c = 0; c < Cc; c++) {
        float a0 = w2[(ty*4+0)*Cc+c], a1 = w2[(ty*4+1)*Cc+c];
        float a2 = w2[(ty*4+2)*Cc+c], a3 = w2[(ty*4+3)*Cc+c];
        #pragma unroll
        for (int j = 0; j < 12; j++) {
            float xv = xs[c*PIX + tx + 16*j];
            acc[0][j] += a0*xv; acc[1][j] += a1*xv; acc[2][j] += a2*xv; acc[3][j] += a3*xv;
        }
    }
    float bo0 = b2[ty*4], bo1 = b2[ty*4+1], bo2 = b2[ty*4+2], bo3 = b2[ty*4+3];
    #pragma unroll
    for (int j = 0; j < 12; j++) {
        int p = tx + 16*j;
        float4 vv = make_float4(acc[0][j]+bo0, acc[1][j]+bo1, acc[2][j]+bo2, acc[3][j]+bo3);
        *(float4*)&g_V[side][bh][w0+p][ty*4] = vv;
        b_VT[side][bh][ty*4+0][w0+p] = __float2bfloat16(vv.x);
        b_VT[side][bh][ty*4+1][w0+p] = __float2bfloat16(vv.y);
        b_VT[side][bh][ty*4+2][w0+p] = __float2bfloat16(vv.z);
        b_VT[side][bh][ty*4+3][w0+p] = __float2bfloat16(vv.w);
    }
}

// ================= K2: attention logits, FFMA2 =================
#define TK 16
__global__ void __launch_bounds__(256) k2_attn()
{
    __shared__ float As[TK][132];
    __shared__ float Bs[TK][132];
    const int bh = blockIdx.z;
    const int v0 = blockIdx.x * 128, w0 = blockIdx.y * 128;
    const int tid = threadIdx.x;
    const int tx = tid & 15, ty = tid >> 4;
    u64 acc2[4][8];
    #pragma unroll
    for (int p = 0; p < 4; p++)
        #pragma unroll
        for (int j = 0; j < 8; j++) acc2[p][j] = 0ULL;

    for (int ck = 0; ck < Cc; ck += TK) {
        #pragma unroll
        for (int r = 0; r < 2; r++) {
            int f = tid + r*256;
            int k = f >> 5, c4 = (f & 31) * 4;
            *(float4*)&As[k][c4] = *(const float4*)&g_Q[0][bh][ck+k][w0+c4];
            *(float4*)&Bs[k][c4] = *(const float4*)&g_Q[1][bh][ck+k][v0+c4];
        }
        __syncthreads();
        #pragma unroll
        for (int k = 0; k < TK; k++) {
            ulonglong2 aA = *(const ulonglong2*)&As[k][ty*4];
            ulonglong2 aB = *(const ulonglong2*)&As[k][64 + ty*4];
            u64 A2[4] = {aA.x, aA.y, aB.x, aB.y};
            float4 b0 = *(const float4*)&Bs[k][tx*4];
            float4 b1 = *(const float4*)&Bs[k][64 + tx*4];
            u64 Bd[8] = {dup2f(b0.x), dup2f(b0.y), dup2f(b0.z), dup2f(b0.w),
                         dup2f(b1.x), dup2f(b1.y), dup2f(b1.z), dup2f(b1.w)};
            #pragma unroll
            for (int p = 0; p < 4; p++)
                #pragma unroll
                for (int j = 0; j < 8; j++) fma2(acc2[p][j], A2[p], Bd[j]);
        }
        __syncthreads();
    }
    const float s = 0.125f;
    #pragma unroll
    for (int p = 0; p < 4; p++) {
        int wlo = w0 + ((p < 2) ? (ty*4 + 2*p) : (64 + ty*4 + 2*(p-2)));
        float2 f[8];
        #pragma unroll
        for (int j = 0; j < 8; j++) f[j] = up2(acc2[p][j]);
        *(float4*)&g_A[bh][wlo][v0 + tx*4] = make_float4(f[0].x*s, f[1].x*s, f[2].x*s, f[3].x*s);
        *(float4*)&g_A[bh][wlo][v0 + 64 + tx*4] = make_float4(f[4].x*s, f[5].x*s, f[6].x*s, f[7].x*s);
        *(float4*)&g_A[bh][wlo+1][v0 + tx*4] = make_float4(f[0].y*s, f[1].y*s, f[2].y*s, f[3].y*s);
        *(float4*)&g_A[bh][wlo+1][v0 + 64 + tx*4] = make_float4(f[4].y*s, f[5].y*s, f[6].y*s, f[7].y*s);
    }
}

// ================= K3a: row stats =================
__global__ void k3a_rowstats()
{
    const int bh = blockIdx.y;
    const int w = blockIdx.x*8 + (threadIdx.x >> 5);
    const int lane = threadIdx.x & 31;
    const float* __restrict__ row = g_A[bh][w];
    float m = -1e30f;
    for (int v = lane; v < Ww; v += 32) m = fmaxf(m, row[v]);
    #pragma unroll
    for (int o = 16; o; o >>= 1) m = fmaxf(m, __shfl_xor_sync(0xffffffffu, m, o));
    float s = 0.f;
    for (int v = lane; v < Ww; v += 32) s += __expf(row[v] - m);
    #pragma unroll
    for (int o = 16; o; o >>= 1) s += __shfl_xor_sync(0xffffffffu, s, o);
    if (!lane) { g_rmax[bh][w] = m; g_rinv[bh][w] = 1.f/s; }
}

// ================= K3b: col stats =================
__global__ void k3b_colstats()
{
    __shared__ float redm[8][32], reds[8][32], redms[8][32];
    const int bh = blockIdx.y;
    const int tid = threadIdx.x;
    const int lane = tid & 31, g = tid >> 5;
    const int v = blockIdx.x*32 + lane;

    float m = -1e30f;
    for (int w = g; w < Ww; w += 8) m = fmaxf(m, g_A[bh][w][v]);
    redm[g][lane] = m;
    __syncthreads();
    if (g == 0) {
        for (int k = 1; k < 8; k++) m = fmaxf(m, redm[k][lane]);
        redm[0][lane] = m;
    }
    __syncthreads();
    m = redm[0][lane];

    float s = 0.f, ms = 0.f;
    for (int w = g; w < Ww; w += 8) {
        float a = g_A[bh][w][v];
        s  += __expf(a - m);
        ms += __expf(a - g_rmax[bh][w]) * g_rinv[bh][w];
    }
    reds[g][lane] = s; redms[g][lane] = ms;
    __syncthreads();
    if (g == 0) {
        for (int k = 1; k < 8; k++) { s += reds[k][lane]; ms += redms[k][lane]; }
        g_cmax[bh][v] = m;
        g_cinv[bh][v] = 1.f/s;
        g_ms_r2l[bh][v] = ms;
    }
}

// ================= K4: write M matrices (fp32 + bf16 row-major) =================
__device__ __forceinline__ uint2 pack4bf(float a, float b, float c, float d) {
    __nv_bfloat162 p0 = __floats2bfloat162_rn(a, b);
    __nv_bfloat162 p1 = __floats2bfloat162_rn(c, d);
    uint2 r;
    r.x = *(u32*)&p0; r.y = *(u32*)&p1;
    return r;
}
__global__ void k4_writeM()
{
    const int bh = blockIdx.y;
    const int u = blockIdx.x*8 + (threadIdx.x >> 5);
    const int lane = threadIdx.x & 31;
    const float rm = g_rmax[bh][u], ri = g_rinv[bh][u];
    const float* __restrict__ row = g_A[bh][u];
    float msum = 0.f;
    #pragma unroll
    for (int it = 0; it < 3; it++) {
        int v = it*128 + lane*4;
        float4 a  = *(const float4*)&row[v];
        float4 cm = *(const float4*)&g_cmax[bh][v];
        float4 ci = *(const float4*)&g_cinv[bh][v];
        float4 m1 = make_float4(__expf(a.x-rm)*ri, __expf(a.y-rm)*ri,
                                __expf(a.z-rm)*ri, __expf(a.w-rm)*ri);
        float4 m2 = make_float4(__expf(a.x-cm.x)*ci.x, __expf(a.y-cm.y)*ci.y,
                                __expf(a.z-cm.z)*ci.z, __expf(a.w-cm.w)*ci.w);
        *(float4*)&g_Mr2l[bh][u][v] = m1;
        *(float4*)&g_MLT[bh][u][v]  = m2;
        *(uint2*)&b_Mr2l[bh][u][v] = pack4bf(m1.x, m1.y, m1.z, m1.w);
        *(uint2*)&b_MLT[bh][u][v]  = pack4bf(m2.x, m2.y, m2.z, m2.w);
        msum += m2.x + m2.y + m2.z + m2.w;
    }
    #pragma unroll
    for (int o = 16; o; o >>= 1) msum += __shfl_xor_sync(0xffffffffu, msum, o);
    if (!lane) g_ms_l2r[bh][u] = msum;
}

// ================= K4T: bf16 -> transposed bf16 =================
__global__ void __launch_bounds__(256) k4t_transpose()
{
    __shared__ __align__(16) __nv_bfloat16 t1[64][68];
    __shared__ __align__(16) __nv_bfloat16 t2[64][68];
    const int bh = blockIdx.z;
    const int v0 = blockIdx.x*64, u0 = blockIdx.y*64;
    const int tid = threadIdx.x;
    const int tx = tid & 15, ty = tid >> 4;
    #pragma unroll
    for (int i = 0; i < 4; i++) {
        int ul = ty*4 + i;
        *(uint2*)&t1[ul][tx*4] = *(const uint2*)&b_Mr2l[bh][u0+ul][v0 + tx*4];
        *(uint2*)&t2[ul][tx*4] = *(const uint2*)&b_MLT[bh][u0+ul][v0 + tx*4];
    }
    __syncthreads();
    #pragma unroll
    for (int i = 0; i < 4; i++) {
        int vl = ty*4 + i;
        const u16* p1r = (const u16*)t1;
        const u16* p2r = (const u16*)t2;
        uint2 o1, o2;
        o1.x = (u32)p1r[(tx*4+0)*68 + vl] | ((u32)p1r[(tx*4+1)*68 + vl] << 16);
        o1.y = (u32)p1r[(tx*4+2)*68 + vl] | ((u32)p1r[(tx*4+3)*68 + vl] << 16);
        o2.x = (u32)p2r[(tx*4+0)*68 + vl] | ((u32)p2r[(tx*4+1)*68 + vl] << 16);
        o2.y = (u32)p2r[(tx*4+2)*68 + vl] | ((u32)p2r[(tx*4+3)*68 + vl] << 16);
        *(uint2*)&b_Mr2lT[bh][v0+vl][u0 + tx*4] = o1;
        *(uint2*)&b_MLTT[bh][v0+vl][u0 + tx*4]  = o2;
    }
}

// ================= MMA helpers =================
#define APAD 40
__device__ __forceinline__ void ldsm4(u32& r0, u32& r1, u32& r2, u32& r3, u32 addr) {
    asm volatile("ldmatrix.sync.aligned.m8n8.x4.shared.b16 {%0,%1,%2,%3}, [%4];"
                 : "=r"(r0), "=r"(r1), "=r"(r2), "=r"(r3) : "r"(addr));
}
__device__ __forceinline__ void mma_bf16(float* c, const u32* a, u32 b0, u32 b1) {
    asm volatile("mma.sync.aligned.m16n8k16.row.col.f32.bf16.bf16.f32 "
                 "{%0,%1,%2,%3}, {%4,%5,%6,%7}, {%8,%9}, {%0,%1,%2,%3};"
                 : "+f"(c[0]), "+f"(c[1]), "+f"(c[2]), "+f"(c[3])
                 : "r"(a[0]), "r"(a[1]), "r"(a[2]), "r"(a[3]), "r"(b0), "r"(b1));
}

// ================= K5: cycle loss via warp MMA (bf16 HMMA) =================
__global__ void __launch_bounds__(256) k5_cycle_mma()
{
    __shared__ __align__(16) __nv_bfloat16 As[128][APAD];
    __shared__ __align__(16) __nv_bfloat16 Bs[128][APAD];
    __shared__ float red[256];
    const int z = blockIdx.z, term = z & 1, bh = z >> 1;
    const int u0 = blockIdx.x*128, w0 = blockIdx.y*128;
    const int tid = threadIdx.x, wid = tid >> 5, lane = tid & 31;
    const int wm = wid >> 2, wn = wid & 3;
    const __nv_bfloat16* __restrict__ Ag = term == 0 ? &b_Mr2l[bh][w0][0] : &b_MLTT[bh][w0][0];
    const __nv_bfloat16* __restrict__ Bg = term == 0 ? &b_MLT[bh][u0][0]  : &b_Mr2lT[bh][u0][0];

    float c[4][4][4];
    #pragma unroll
    for (int mt = 0; mt < 4; mt++)
        #pragma unroll
        for (int nt = 0; nt < 4; nt++)
            #pragma unroll
            for (int i = 0; i < 4; i++) c[mt][nt][i] = 0.f;

    const u32 a_base = smem_u32(As), b_base = smem_u32(Bs);
    const u32 a_row = wm*64 + (lane & 15);
    const u32 a_coff = (lane >> 4) * 16;
    const u32 b_row = wn*32 + (lane & 7) + ((lane >> 4) << 3);
    const u32 b_coff = ((lane >> 3) & 1) * 16;

    for (int ch = 0; ch < 12; ch++) {
        #pragma unroll
        for (int p = 0; p < 2; p++) {
            int idx = tid + p*256;
            int row = idx >> 2, seg = idx & 3;
            const long go = (long)row*Ww + ch*32 + seg*8;
            uint4 va = *(const uint4*)(Ag + go);
            uint4 vb = *(const uint4*)(Bg + go);
            *(uint2*)&As[row][seg*8]     = make_uint2(va.x, va.y);
            *(uint2*)&As[row][seg*8 + 4] = make_uint2(va.z, va.w);
            *(uint2*)&Bs[row][seg*8]     = make_uint2(vb.x, vb.y);
            *(uint2*)&Bs[row][seg*8 + 4] = make_uint2(vb.z, vb.w);
        }
        __syncthreads();
        #pragma unroll
        for (int ks = 0; ks < 2; ks++) {
            const u32 kb = ks*32;
            u32 bf[2][4];
            #pragma unroll
            for (int hgrp = 0; hgrp < 2; hgrp++) {
                u32 addr = b_base + (b_row + hgrp*16)*(APAD*2) + kb + b_coff;
                ldsm4(bf[hgrp][0], bf[hgrp][1], bf[hgrp][2], bf[hgrp][3], addr);
            }
            #pragma unroll
            for (int mt = 0; mt < 4; mt++) {
                u32 a[4];
                u32 addr = a_base + (a_row + mt*16)*(APAD*2) + kb + a_coff;
                ldsm4(a[0], a[1], a[2], a[3], addr);
                #pragma unroll
                for (int nt = 0; nt < 4; nt++)
                    mma_bf16(c[mt][nt], a, bf[nt >> 1][(nt & 1)*2], bf[nt >> 1][(nt & 1)*2 + 1]);
            }
        }
        __syncthreads();
    }

    const float* __restrict__ msrow = (term == 0) ? g_ms_l2r[bh] : g_ms_r2l[bh];
    float lsum = 0.f;
    #pragma unroll
    for (int nt = 0; nt < 4; nt++) {
        #pragma unroll
        for (int jj = 0; jj < 2; jj++) {
            int u = u0 + wn*32 + nt*8 + (lane & 3)*2 + jj;
            float mk = (msrow[u] > 0.1f) ? 1.f : 0.f;
            #pragma unroll
            for (int mt = 0; mt < 4; mt++) {
                #pragma unroll
                for (int hh = 0; hh < 2; hh++) {
                    int w = w0 + wm*64 + mt*16 + (lane >> 2) + hh*8;
                    float dv = c[mt][nt][hh*2 + jj];
                    lsum += mk * fabsf(dv - ((w == u) ? 1.f : 0.f));
                }
            }
        }
    }
    red[tid] = lsum; __syncthreads();
    for (int s = 128; s; s >>= 1) { if (tid < s) red[tid] += red[tid+s]; __syncthreads(); }
    if (!tid) g_p_cyc[z*9 + blockIdx.y*3 + blockIdx.x] = red[0];
}

// ================= K6: outputs via warp MMA (bf16) =================
__global__ void __launch_bounds__(256) k6_mma(const float* __restrict__ x,
                                              const float* __restrict__ bg,
                                              float* __restrict__ out, int side)
{
    __shared__ __align__(16) __nv_bfloat16 As[128][APAD];
    __shared__ __align__(16) __nv_bfloat16 Bs[64][APAD];
    const int bh = blockIdx.y;
    const int b = bh / Hh, h = bh % Hh;
    const int w0 = blockIdx.x * 128;
    const int tid = threadIdx.x, wid = tid >> 5, lane = tid & 31;
    const int wm = wid >> 2, wn = wid & 3;
    const __nv_bfloat16* __restrict__ Ag = side == 0 ? &b_Mr2l[bh][w0][0] : &b_MLTT[bh][w0][0];
    const __nv_bfloat16* __restrict__ Bg = &b_VT[side == 0 ? 1 : 0][bh][0][0];

    float c[4][2][4];
    #pragma unroll
    for (int mt = 0; mt < 4; mt++)
        #pragma unroll
        for (int nt = 0; nt < 2; nt++)
            #pragma unroll
            for (int i = 0; i < 4; i++) c[mt][nt][i] = 0.f;

    const u32 a_base = smem_u32(As), b_base = smem_u32(Bs);
    const u32 a_row = wm*64 + (lane & 15);
    const u32 a_coff = (lane >> 4) * 16;
    const u32 b_row = wn*16 + (lane & 7) + ((lane >> 4) << 3);
    const u32 b_coff = ((lane >> 3) & 1) * 16;

    for (int ch = 0; ch < 12; ch++) {
        #pragma unroll
        for (int p = 0; p < 2; p++) {
            int idx = tid + p*256;
            int row = idx >> 2, seg = idx & 3;
            uint4 va = *(const uint4*)(Ag + (long)row*Ww + ch*32 + seg*8);
            *(uint2*)&As[row][seg*8]     = make_uint2(va.x, va.y);
            *(uint2*)&As[row][seg*8 + 4] = make_uint2(va.z, va.w);
        }
        {
            int row = tid >> 2, seg = tid & 3;
            uint4 vb = *(const uint4*)(Bg + (long)row*Ww + ch*32 + seg*8);
            *(uint2*)&Bs[row][seg*8]     = make_uint2(vb.x, vb.y);
            *(uint2*)&Bs[row][seg*8 + 4] = make_uint2(vb.z, vb.w);
        }
        __syncthreads();
        #pragma unroll
        for (int ks = 0; ks < 2; ks++) {
            const u32 kb = ks*32;
            u32 bfr[4];
            ldsm4(bfr[0], bfr[1], bfr[2], bfr[3], b_base + b_row*(APAD*2) + kb + b_coff);
            #pragma unroll
            for (int mt = 0; mt < 4; mt++) {
                u32 a[4];
                ldsm4(a[0], a[1], a[2], a[3], a_base + (a_row + mt*16)*(APAD*2) + kb + a_coff);
                mma_bf16(c[mt][0], a, bfr[0], bfr[1]);
                mma_bf16(c[mt][1], a, bfr[2], bfr[3]);
            }
        }
        __syncthreads();
    }

    #pragma unroll
    for (int nt = 0; nt < 2; nt++) {
        #pragma unroll
        for (int jj = 0; jj < 2; jj++) {
            int cc = wn*16 + nt*8 + (lane & 3)*2 + jj;
            float bgc = bg[cc];
            #pragma unroll
            for (int mt = 0; mt < 4; mt++) {
                #pragma unroll
                for (int hh = 0; hh < 2; hh++) {
                    int w = w0 + wm*64 + mt*16 + (lane >> 2) + hh*8;
                    long gi = (((long)b*Cc + cc)*Hh + h)*Ww + w;
                    out[gi] = x[gi] + bgc * c[mt][nt][hh*2 + jj];
                }
            }
        }
    }
}

// ================= K7a =================
__global__ void k7a_photo1(const float* __restrict__ LRl, const float* __restrict__ LRr)
{
    __shared__ float lr[3][Ww];
    __shared__ float r8[8];
    const int bh = blockIdx.y;
    const int b = bh / Hh, h = bh % Hh;
    const int w = blockIdx.x*8 + (threadIdx.x >> 5);
    const int lane = threadIdx.x & 31;
    for (int idx = threadIdx.x; idx < 3*Ww; idx += 256) {
        int ch = idx / Ww, v = idx % Ww;
        lr[ch][v] = LRr[(((long)b*3 + ch)*Hh + h)*Ww + v];
    }
    __syncthreads();
    float a0 = 0.f, a1 = 0.f, a2 = 0.f;
    const float* __restrict__ mrow = g_Mr2l[bh][w];
    for (int v = lane; v < Ww; v += 32) {
        float m = mrow[v];
        a0 += m*lr[0][v]; a1 += m*lr[1][v]; a2 += m*lr[2][v];
    }
    #pragma unroll
    for (int o = 16; o; o >>= 1) {
        a0 += __shfl_xor_sync(0xffffffffu, a0, o);
        a1 += __shfl_xor_sync(0xffffffffu, a1, o);
        a2 += __shfl_xor_sync(0xffffffffu, a2, o);
    }
    if (!lane) {
        float mk = (g_ms_l2r[bh][w] > 0.1f) ? 1.f : 0.f;
        long base = (((long)b*3)*Hh + h)*Ww + w;
        float part = mk * (fabsf(LRl[base] - a0)
                         + fabsf(LRl[base + (long)Hh*Ww] - a1)
                         + fabsf(LRl[base + 2L*Hh*Ww] - a2));
        r8[threadIdx.x >> 5] = part;
    }
    __syncthreads();
    if (threadIdx.x == 0) {
        float s = 0.f;
        for (int k = 0; k < 8; k++) s += r8[k];
        g_p_ph1[bh*48 + blockIdx.x] = s;
    }
}

// ================= K7b =================
__global__ void k7b_photo2(const float* __restrict__ LRl, const float* __restrict__ LRr)
{
    __shared__ float la[3][Ww], lb[3][Ww];
    __shared__ float red[128];
    const int bh = blockIdx.x;
    const int b = bh / Hh, h = bh % Hh;
    const int tid = threadIdx.x;
    for (int idx = tid; idx < 3*Ww; idx += 128) {
        int ch = idx / Ww, w = idx % Ww;
        long gi = (((long)b*3 + ch)*Hh + h)*Ww + w;
        la[ch][w] = LRl[gi];
        lb[ch][w] = LRr[gi];
    }
    __syncthreads();
    float acc[3][3] = {};
    for (int v = 0; v < Ww; v++) {
        const float* __restrict__ mr = g_MLT[bh][v];
        float l0 = la[0][v], l1 = la[1][v], l2 = la[2][v];
        #pragma unroll
        for (int s = 0; s < 3; s++) {
            float m = mr[tid + s*128];
            acc[s][0] += m*l0; acc[s][1] += m*l1; acc[s][2] += m*l2;
        }
    }
    float part = 0.f;
    #pragma unroll
    for (int s = 0; s < 3; s++) {
        int w = tid + s*128;
        float mk = (g_ms_r2l[bh][w] > 0.1f) ? 1.f : 0.f;
        part += mk * (fabsf(lb[0][w] - acc[s][0])
                    + fabsf(lb[1][w] - acc[s][1])
                    + fabsf(lb[2][w] - acc[s][2]));
    }
    red[tid] = part; __syncthreads();
    for (int s = 64; s; s >>= 1) { if (tid < s) red[tid] += red[tid+s]; __syncthreads(); }
    if (!tid) g_p_ph2[bh] = red[0];
}

// ================= K8 =================
__global__ void k8_smooth()
{
    __shared__ float redh[256], redw[256];
    const int mat = blockIdx.z, bh = blockIdx.y, w0 = blockIdx.x*16;
    const int h = bh % Hh;
    const float* __restrict__ M = mat ? &g_MLT[0][0][0] : &g_Mr2l[0][0][0];
    const int tid = threadIdx.x;
    float sh = 0.f, sw = 0.f;
    for (int idx = tid; idx < 16*Ww; idx += 256) {
        int w = w0 + idx / Ww, v = idx % Ww;
        long base = ((long)bh*Ww + w)*Ww + v;
        float m = M[base];
        if (h < Hh - 1) sh += fabsf(m - M[base + (long)Ww*Ww]);
        if (w < Ww - 1 && v < Ww - 1) sw += fabsf(m - M[base + Ww + 1]);
    }
    redh[tid] = sh; redw[tid] = sw; __syncthreads();
    for (int s = 128; s; s >>= 1) {
        if (tid < s) { redh[tid] += redh[tid+s]; redw[tid] += redw[tid+s]; }
        __syncthreads();
    }
    if (!tid) {
        int slot = (mat*BHn + bh)*24 + blockIdx.x;
        g_p_smh[slot] = redh[0];
        g_p_smw[slot] = redw[0];
    }
}

// ================= K9 =================
__global__ void k9_final(const float* __restrict__ loss_in, float* __restrict__ out_loss)
{
    __shared__ double red[256];
    const int tid = threadIdx.x;
    double acc[4] = {0.0, 0.0, 0.0, 0.0};
    for (int i = tid; i < NP_CYC; i += 256) acc[0] += (double)g_p_cyc[i];
    for (int i = tid; i < NP_PH1; i += 256) acc[1] += (double)g_p_ph1[i];
    for (int i = tid; i < NP_PH2; i += 256) acc[1] += (double)g_p_ph2[i];
    for (int i = tid; i < NP_SM;  i += 256) acc[2] += (double)g_p_smh[i];
    for (int i = tid; i < NP_SM;  i += 256) acc[3] += (double)g_p_smw[i];
    double tot[4];
    for (int a = 0; a < 4; a++) {
        red[tid] = acc[a]; __syncthreads();
        for (int s = 128; s; s >>= 1) { if (tid < s) red[tid] += red[tid+s]; __syncthreads(); }
        tot[a] = red[0]; __syncthreads();
    }
    if (!tid) {
        double lc = tot[0] / ((double)Bz*Hh*Ww*Ww);
        double lp = tot[1] / ((double)Bz*3*Hh*Ww);
        double lh = tot[2] / ((double)Bz*(Hh-1)*Ww*Ww);
        double lw = tot[3] / ((double)Bz*Hh*(Ww-1)*(Ww-1));
        out_loss[0] = (float)((double)loss_in[0] + 0.0025*(lp + 0.1*(lw + lh) + lc));
    }
}

extern "C" void kernel_launch(void* const* d_in, const int* in_sizes, int n_in,
                              void* d_out, int out_size)
{
    (void)in_sizes; (void)n_in; (void)out_size;
    const float* x_l   = (const float*)d_in[0];
    const float* x_r   = (const float*)d_in[1];
    const float* LRl   = (const float*)d_in[2];
    const float* LRr   = (const float*)d_in[3];
    const float* lossi = (const float*)d_in[4];
    const float* nlw = (const float*)d_in[5];
    const float* nlb = (const float*)d_in[6];
    const float* nrw = (const float*)d_in[7];
    const float* nrb = (const float*)d_in[8];
    const float* lp1w = (const float*)d_in[9];
    const float* lp1b = (const float*)d_in[10];
    const float* rp1w = (const float*)d_in[11];
    const float* rp1b = (const float*)d_in[12];
    const float* lp2w = (const float*)d_in[13];
    const float* lp2b = (const float*)d_in[14];
    const float* rp2w = (const float*)d_in[15];
    const float* rp2b = (const float*)d_in[16];
    const float* beta  = (const float*)d_in[17];
    const float* gamma = (const float*)d_in[18];

    float* out = (float*)d_out;
    float* out_xl   = out;
    float* out_xr   = out + NX;
    float* out_lrl  = out + 2L*NX;
    float* out_lrr  = out + 2L*NX + NLR;
    float* out_loss = out + 2L*NX + 2L*NLR;

    const size_t smem1 = (size_t)(Cc*PIX + 2*Cc*Cc + 2*Cc + 2*PIX) * sizeof(float);
    cudaFuncSetAttribute(k1_lnproj, cudaFuncAttributeMaxDynamicSharedMemorySize, (int)smem1);

    k1_lnproj<<<dim3(2, BHn), 256, smem1>>>(x_l, nlw, nlb, lp1w, lp1b, lp2w, lp2b, 0);
    k1_lnproj<<<dim3(2, BHn), 256, smem1>>>(x_r, nrw, nrb, rp1w, rp1b, rp2w, rp2b, 1);
    k2_attn<<<dim3(3, 3, BHn), 256>>>();
    k3a_rowstats<<<dim3(48, BHn), 256>>>();
    k3b_colstats<<<dim3(12, BHn), 256>>>();
    k4_writeM<<<dim3(48, BHn), 256>>>();
    k4t_transpose<<<dim3(6, 6, BHn), 256>>>();
    k5_cycle_mma<<<dim3(3, 3, BHn*2), 256>>>();
    k6_mma<<<dim3(3, BHn), 256>>>(x_l, beta, out_xl, 0);
    k6_mma<<<dim3(3, BHn), 256>>>(x_r, gamma, out_xr, 1);
    k7a_photo1<<<dim3(48, BHn), 256>>>(LRl, LRr);
    k7b_photo2<<<BHn, 128>>>(LRl, LRr);
    k8_smooth<<<dim3(24, BHn, 2), 256>>>();
    cudaMemcpyAsync(out_lrl, LRl, (size_t)NLR*sizeof(float), cudaMemcpyDeviceToDevice, 0);
    cudaMemcpyAsync(out_lrr, LRr, (size_t)NLR*sizeof(float), cudaMemcpyDeviceToDevice, 0);
    k9_final<<<1, 256>>>(lossi, out_loss);
}

// round 10
// speedup vs baseline: 2.1298x; 1.0629x over previous
#include <cuda_runtime.h>
#include <cuda_bf16.h>
#include <math.h>

#define Bz 4
#define Cc 64
#define Hh 96
#define Ww 384
#define BHn (Bz*Hh)
#define NX (Bz*Cc*Hh*Ww)
#define NLR (Bz*3*Hh*Ww)
#define EPS 1e-6f

typedef unsigned long long u64;
typedef unsigned int u32;
typedef unsigned short u16;
__device__ __forceinline__ u64 dup2f(float x) {
    u64 r; asm("mov.b64 %0, {%1, %1};" : "=l"(r) : "f"(x)); return r;
}
__device__ __forceinline__ void fma2(u64 &d, u64 a, u64 b) {
    asm("fma.rn.f32x2 %0, %1, %2, %0;" : "+l"(d) : "l"(a), "l"(b));
}
__device__ __forceinline__ float2 up2(u64 v) {
    float2 r; asm("mov.b64 {%0, %1}, %2;" : "=f"(r.x), "=f"(r.y) : "l"(v)); return r;
}
__device__ __forceinline__ u32 smem_u32(const void* p) {
    u32 a; asm("{ .reg .u64 t; cvta.to.shared.u64 t, %1; cvt.u32.u64 %0, t; }" : "=r"(a) : "l"(p));
    return a;
}

__device__ __align__(16) float g_Q[2][BHn][Cc][Ww];
__device__ __align__(16) float g_A[BHn][Ww][Ww];
__device__ __align__(16) __nv_bfloat16 b_Mr2l[BHn][Ww][Ww];
__device__ __align__(16) __nv_bfloat16 b_MLT[BHn][Ww][Ww];
__device__ __align__(16) __nv_bfloat16 b_Mr2lT[BHn][Ww][Ww];
__device__ __align__(16) __nv_bfloat16 b_MLTT[BHn][Ww][Ww];
__device__ __align__(16) __nv_bfloat16 b_VT[2][BHn][Cc][Ww];
__device__ __align__(16) float g_rmax[BHn][Ww];
__device__ __align__(16) float g_rinv[BHn][Ww];
__device__ __align__(16) float g_cmax[BHn][Ww];
__device__ __align__(16) float g_cinv[BHn][Ww];
__device__ __align__(16) float g_ms_r2l[BHn][Ww];
__device__ __align__(16) float g_ms_l2r[BHn][Ww];

#define NP_CYC (2*BHn*9)
#define NP_PH1 (48*BHn)
#define NP_PH2 (BHn)
#define NP_SM  (2*BHn*24)
__device__ float g_p_cyc[NP_CYC];
__device__ float g_p_ph1[NP_PH1];
__device__ float g_p_ph2[NP_PH2];
__device__ float g_p_smh[NP_SM];
__device__ float g_p_smw[NP_SM];

// ================= K1: LN + both 1x1 projections (Q fp32, V -> bf16 V^T) =================
#define PIX 192
__global__ void k1_lnproj(const float* __restrict__ x,
                          const float* __restrict__ nw, const float* __restrict__ nb,
                          const float* __restrict__ p1, const float* __restrict__ b1,
                          const float* __restrict__ p2, const float* __restrict__ b2,
                          int side)
{
    extern __shared__ float sm[];
    float* xs   = sm;
    float* w1   = xs + Cc*PIX;
    float* w2   = w1 + Cc*Cc;
    float* s1   = w2 + Cc*Cc;
    float* t1   = s1 + Cc;
    float* mval = t1 + Cc;
    float* rval = mval + PIX;

    const int bh = blockIdx.y;
    const int b = bh / Hh, h = bh % Hh;
    const int w0 = blockIdx.x * PIX;
    const int tid = threadIdx.x;

    for (int idx = tid; idx < Cc*Cc; idx += 256) {
        int c = idx & 63;
        w1[idx] = p1[idx] * nw[c];
        w2[idx] = p2[idx];
    }
    for (int idx = tid; idx < Cc*PIX; idx += 256) {
        int c = idx / PIX, p = idx % PIX;
        xs[idx] = x[(((long)b*Cc + c)*Hh + h)*Ww + w0 + p];
    }
    __syncthreads();

    for (int o = tid; o < Cc; o += 256) {
        float s = 0.f, t = b1[o];
        for (int c = 0; c < Cc; c++) { s += w1[o*Cc + c]; t += p1[o*Cc + c]*nb[c]; }
        s1[o] = s; t1[o] = t;
    }
    for (int p = tid; p < PIX; p += 256) {
        float s = 0.f, q = 0.f;
        for (int c = 0; c < Cc; c++) { float v = xs[c*PIX + p]; s += v; q += v*v; }
        float mu = s * (1.f/Cc);
        float var = q*(1.f/Cc) - mu*mu;
        float r = rsqrtf(var + EPS);
        rval[p] = r; mval[p] = -r*mu;
    }
    __syncthreads();

    const int tx = tid & 15, ty = tid >> 4;
    float acc[4][12];

    #pragma unroll
    for (int i = 0; i < 4; i++)
        #pragma unroll
        for (int j = 0; j < 12; j++) acc[i][j] = 0.f;
    for (int c = 0; c < Cc; c++) {
        float a0 = w1[(ty*4+0)*Cc+c], a1 = w1[(ty*4+1)*Cc+c];
        float a2 = w1[(ty*4+2)*Cc+c], a3 = w1[(ty*4+3)*Cc+c];
        #pragma unroll
        for (int j = 0; j < 12; j++) {
            float xv = xs[c*PIX + tx + 16*j];
            acc[0][j] += a0*xv; acc[1][j] += a1*xv; acc[2][j] += a2*xv; acc[3][j] += a3*xv;
        }
    }
    #pragma unroll
    for (int i = 0; i < 4; i++) {
        int o = ty*4 + i;
        float so = s1[o], to = t1[o];
        #pragma unroll
        for (int j = 0; j < 12; j++) {
            int p = tx + 16*j;
            g_Q[side][bh][o][w0+p] = rval[p]*acc[i][j] + mval[p]*so + to;
        }
    }

    #pragma unroll
    for (int i = 0; i < 4; i++)
        #pragma unroll
        for (int j = 0; j < 12; j++) acc[i][j] = 0.f;
    for (int c = 0; c < Cc; c++) {
        float a0 = w2[(ty*4+0)*Cc+c], a1 = w2[(ty*4+1)*Cc+c];
        float a2 = w2[(ty*4+2)*Cc+c], a3 = w2[(ty*4+3)*Cc+c];
        #pragma unroll
        for (int j = 0; j < 12; j++) {
            float xv = xs[c*PIX + tx + 16*j];
            acc[0][j] += a0*xv; acc[1][j] += a1*xv; acc[2][j] += a2*xv; acc[3][j] += a3*xv;
        }
    }
    float bo0 = b2[ty*4], bo1 = b2[ty*4+1], bo2 = b2[ty*4+2], bo3 = b2[ty*4+3];
    #pragma unroll
    for (int j = 0; j < 12; j++) {
        int p = tx + 16*j;
        b_VT[side][bh][ty*4+0][w0+p] = __float2bfloat16(acc[0][j]+bo0);
        b_VT[side][bh][ty*4+1][w0+p] = __float2bfloat16(acc[1][j]+bo1);
        b_VT[side][bh][ty*4+2][w0+p] = __float2bfloat16(acc[2][j]+bo2);
        b_VT[side][bh][ty*4+3][w0+p] = __float2bfloat16(acc[3][j]+bo3);
    }
}

// ================= K2: attention logits, FFMA2 =================
#define TK 16
__global__ void __launch_bounds__(256) k2_attn()
{
    __shared__ float As[TK][132];
    __shared__ float Bs[TK][132];
    const int bh = blockIdx.z;
    const int v0 = blockIdx.x * 128, w0 = blockIdx.y * 128;
    const int tid = threadIdx.x;
    const int tx = tid & 15, ty = tid >> 4;
    u64 acc2[4][8];
    #pragma unroll
    for (int p = 0; p < 4; p++)
        #pragma unroll
        for (int j = 0; j < 8; j++) acc2[p][j] = 0ULL;

    for (int ck = 0; ck < Cc; ck += TK) {
        #pragma unroll
        for (int r = 0; r < 2; r++) {
            int f = tid + r*256;
            int k = f >> 5, c4 = (f & 31) * 4;
            *(float4*)&As[k][c4] = *(const float4*)&g_Q[0][bh][ck+k][w0+c4];
            *(float4*)&Bs[k][c4] = *(const float4*)&g_Q[1][bh][ck+k][v0+c4];
        }
        __syncthreads();
        #pragma unroll
        for (int k = 0; k < TK; k++) {
            ulonglong2 aA = *(const ulonglong2*)&As[k][ty*4];
            ulonglong2 aB = *(const ulonglong2*)&As[k][64 + ty*4];
            u64 A2[4] = {aA.x, aA.y, aB.x, aB.y};
            float4 b0 = *(const float4*)&Bs[k][tx*4];
            float4 b1 = *(const float4*)&Bs[k][64 + tx*4];
            u64 Bd[8] = {dup2f(b0.x), dup2f(b0.y), dup2f(b0.z), dup2f(b0.w),
                         dup2f(b1.x), dup2f(b1.y), dup2f(b1.z), dup2f(b1.w)};
            #pragma unroll
            for (int p = 0; p < 4; p++)
                #pragma unroll
                for (int j = 0; j < 8; j++) fma2(acc2[p][j], A2[p], Bd[j]);
        }
        __syncthreads();
    }
    const float s = 0.125f;
    #pragma unroll
    for (int p = 0; p < 4; p++) {
        int wlo = w0 + ((p < 2) ? (ty*4 + 2*p) : (64 + ty*4 + 2*(p-2)));
        float2 f[8];
        #pragma unroll
        for (int j = 0; j < 8; j++) f[j] = up2(acc2[p][j]);
        *(float4*)&g_A[bh][wlo][v0 + tx*4] = make_float4(f[0].x*s, f[1].x*s, f[2].x*s, f[3].x*s);
        *(float4*)&g_A[bh][wlo][v0 + 64 + tx*4] = make_float4(f[4].x*s, f[5].x*s, f[6].x*s, f[7].x*s);
        *(float4*)&g_A[bh][wlo+1][v0 + tx*4] = make_float4(f[0].y*s, f[1].y*s, f[2].y*s, f[3].y*s);
        *(float4*)&g_A[bh][wlo+1][v0 + 64 + tx*4] = make_float4(f[4].y*s, f[5].y*s, f[6].y*s, f[7].y*s);
    }
}

// ================= K3a: row stats =================
__global__ void k3a_rowstats()
{
    const int bh = blockIdx.y;
    const int w = blockIdx.x*8 + (threadIdx.x >> 5);
    const int lane = threadIdx.x & 31;
    const float* __restrict__ row = g_A[bh][w];
    float m = -1e30f;
    for (int v = lane; v < Ww; v += 32) m = fmaxf(m, row[v]);
    #pragma unroll
    for (int o = 16; o; o >>= 1) m = fmaxf(m, __shfl_xor_sync(0xffffffffu, m, o));
    float s = 0.f;
    for (int v = lane; v < Ww; v += 32) s += __expf(row[v] - m);
    #pragma unroll
    for (int o = 16; o; o >>= 1) s += __shfl_xor_sync(0xffffffffu, s, o);
    if (!lane) { g_rmax[bh][w] = m; g_rinv[bh][w] = 1.f/s; }
}

// ================= K3b: col stats =================
__global__ void k3b_colstats()
{
    __shared__ float redm[8][32], reds[8][32], redms[8][32];
    const int bh = blockIdx.y;
    const int tid = threadIdx.x;
    const int lane = tid & 31, g = tid >> 5;
    const int v = blockIdx.x*32 + lane;

    float m = -1e30f;
    for (int w = g; w < Ww; w += 8) m = fmaxf(m, g_A[bh][w][v]);
    redm[g][lane] = m;
    __syncthreads();
    if (g == 0) {
        for (int k = 1; k < 8; k++) m = fmaxf(m, redm[k][lane]);
        redm[0][lane] = m;
    }
    __syncthreads();
    m = redm[0][lane];

    float s = 0.f, ms = 0.f;
    for (int w = g; w < Ww; w += 8) {
        float a = g_A[bh][w][v];
        s  += __expf(a - m);
        ms += __expf(a - g_rmax[bh][w]) * g_rinv[bh][w];
    }
    reds[g][lane] = s; redms[g][lane] = ms;
    __syncthreads();
    if (g == 0) {
        for (int k = 1; k < 8; k++) { s += reds[k][lane]; ms += redms[k][lane]; }
        g_cmax[bh][v] = m;
        g_cinv[bh][v] = 1.f/s;
        g_ms_r2l[bh][v] = ms;
    }
}

// ================= K4: write M matrices (bf16 row-major only) =================
__device__ __forceinline__ uint2 pack4bf(float a, float b, float c, float d) {
    __nv_bfloat162 p0 = __floats2bfloat162_rn(a, b);
    __nv_bfloat162 p1 = __floats2bfloat162_rn(c, d);
    uint2 r;
    r.x = *(u32*)&p0; r.y = *(u32*)&p1;
    return r;
}
__global__ void k4_writeM()
{
    const int bh = blockIdx.y;
    const int u = blockIdx.x*8 + (threadIdx.x >> 5);
    const int lane = threadIdx.x & 31;
    const float rm = g_rmax[bh][u], ri = g_rinv[bh][u];
    const float* __restrict__ row = g_A[bh][u];
    float msum = 0.f;
    #pragma unroll
    for (int it = 0; it < 3; it++) {
        int v = it*128 + lane*4;
        float4 a  = *(const float4*)&row[v];
        float4 cm = *(const float4*)&g_cmax[bh][v];
        float4 ci = *(const float4*)&g_cinv[bh][v];
        float4 m1 = make_float4(__expf(a.x-rm)*ri, __expf(a.y-rm)*ri,
                                __expf(a.z-rm)*ri, __expf(a.w-rm)*ri);
        float4 m2 = make_float4(__expf(a.x-cm.x)*ci.x, __expf(a.y-cm.y)*ci.y,
                                __expf(a.z-cm.z)*ci.z, __expf(a.w-cm.w)*ci.w);
        *(uint2*)&b_Mr2l[bh][u][v] = pack4bf(m1.x, m1.y, m1.z, m1.w);
        *(uint2*)&b_MLT[bh][u][v]  = pack4bf(m2.x, m2.y, m2.z, m2.w);
        msum += m2.x + m2.y + m2.z + m2.w;
    }
    #pragma unroll
    for (int o = 16; o; o >>= 1) msum += __shfl_xor_sync(0xffffffffu, msum, o);
    if (!lane) g_ms_l2r[bh][u] = msum;
}

// ================= K4T: bf16 -> transposed bf16 =================
__global__ void __launch_bounds__(256) k4t_transpose()
{
    __shared__ __align__(16) __nv_bfloat16 t1[64][68];
    __shared__ __align__(16) __nv_bfloat16 t2[64][68];
    const int bh = blockIdx.z;
    const int v0 = blockIdx.x*64, u0 = blockIdx.y*64;
    const int tid = threadIdx.x;
    const int tx = tid & 15, ty = tid >> 4;
    #pragma unroll
    for (int i = 0; i < 4; i++) {
        int ul = ty*4 + i;
        *(uint2*)&t1[ul][tx*4] = *(const uint2*)&b_Mr2l[bh][u0+ul][v0 + tx*4];
        *(uint2*)&t2[ul][tx*4] = *(const uint2*)&b_MLT[bh][u0+ul][v0 + tx*4];
    }
    __syncthreads();
    #pragma unroll
    for (int i = 0; i < 4; i++) {
        int vl = ty*4 + i;
        const u16* p1r = (const u16*)t1;
        const u16* p2r = (const u16*)t2;
        uint2 o1, o2;
        o1.x = (u32)p1r[(tx*4+0)*68 + vl] | ((u32)p1r[(tx*4+1)*68 + vl] << 16);
        o1.y = (u32)p1r[(tx*4+2)*68 + vl] | ((u32)p1r[(tx*4+3)*68 + vl] << 16);
        o2.x = (u32)p2r[(tx*4+0)*68 + vl] | ((u32)p2r[(tx*4+1)*68 + vl] << 16);
        o2.y = (u32)p2r[(tx*4+2)*68 + vl] | ((u32)p2r[(tx*4+3)*68 + vl] << 16);
        *(uint2*)&b_Mr2lT[bh][v0+vl][u0 + tx*4] = o1;
        *(uint2*)&b_MLTT[bh][v0+vl][u0 + tx*4]  = o2;
    }
}

// ================= MMA helpers =================
#define APAD 40
__device__ __forceinline__ void ldsm4(u32& r0, u32& r1, u32& r2, u32& r3, u32 addr) {
    asm volatile("ldmatrix.sync.aligned.m8n8.x4.shared.b16 {%0,%1,%2,%3}, [%4];"
                 : "=r"(r0), "=r"(r1), "=r"(r2), "=r"(r3) : "r"(addr));
}
__device__ __forceinline__ void mma_bf16(float* c, const u32* a, u32 b0, u32 b1) {
    asm volatile("mma.sync.aligned.m16n8k16.row.col.f32.bf16.bf16.f32 "
                 "{%0,%1,%2,%3}, {%4,%5,%6,%7}, {%8,%9}, {%0,%1,%2,%3};"
                 : "+f"(c[0]), "+f"(c[1]), "+f"(c[2]), "+f"(c[3])
                 : "r"(a[0]), "r"(a[1]), "r"(a[2]), "r"(a[3]), "r"(b0), "r"(b1));
}

// ================= K5: cycle loss via warp MMA (bf16 HMMA) =================
__global__ void __launch_bounds__(256) k5_cycle_mma()
{
    __shared__ __align__(16) __nv_bfloat16 As[128][APAD];
    __shared__ __align__(16) __nv_bfloat16 Bs[128][APAD];
    __shared__ float red[256];
    const int z = blockIdx.z, term = z & 1, bh = z >> 1;
    const int u0 = blockIdx.x*128, w0 = blockIdx.y*128;
    const int tid = threadIdx.x, wid = tid >> 5, lane = tid & 31;
    const int wm = wid >> 2, wn = wid & 3;
    const __nv_bfloat16* __restrict__ Ag = term == 0 ? &b_Mr2l[bh][w0][0] : &b_MLTT[bh][w0][0];
    const __nv_bfloat16* __restrict__ Bg = term == 0 ? &b_MLT[bh][u0][0]  : &b_Mr2lT[bh][u0][0];

    float c[4][4][4];
    #pragma unroll
    for (int mt = 0; mt < 4; mt++)
        #pragma unroll
        for (int nt = 0; nt < 4; nt++)
            #pragma unroll
            for (int i = 0; i < 4; i++) c[mt][nt][i] = 0.f;

    const u32 a_base = smem_u32(As), b_base = smem_u32(Bs);
    const u32 a_row = wm*64 + (lane & 15);
    const u32 a_coff = (lane >> 4) * 16;
    const u32 b_row = wn*32 + (lane & 7) + ((lane >> 4) << 3);
    const u32 b_coff = ((lane >> 3) & 1) * 16;

    for (int ch = 0; ch < 12; ch++) {
        #pragma unroll
        for (int p = 0; p < 2; p++) {
            int idx = tid + p*256;
            int row = idx >> 2, seg = idx & 3;
            const long go = (long)row*Ww + ch*32 + seg*8;
            uint4 va = *(const uint4*)(Ag + go);
            uint4 vb = *(const uint4*)(Bg + go);
            *(uint2*)&As[row][seg*8]     = make_uint2(va.x, va.y);
            *(uint2*)&As[row][seg*8 + 4] = make_uint2(va.z, va.w);
            *(uint2*)&Bs[row][seg*8]     = make_uint2(vb.x, vb.y);
            *(uint2*)&Bs[row][seg*8 + 4] = make_uint2(vb.z, vb.w);
        }
        __syncthreads();
        #pragma unroll
        for (int ks = 0; ks < 2; ks++) {
            const u32 kb = ks*32;
            u32 bf[2][4];
            #pragma unroll
            for (int hgrp = 0; hgrp < 2; hgrp++) {
                u32 addr = b_base + (b_row + hgrp*16)*(APAD*2) + kb + b_coff;
                ldsm4(bf[hgrp][0], bf[hgrp][1], bf[hgrp][2], bf[hgrp][3], addr);
            }
            #pragma unroll
            for (int mt = 0; mt < 4; mt++) {
                u32 a[4];
                u32 addr = a_base + (a_row + mt*16)*(APAD*2) + kb + a_coff;
                ldsm4(a[0], a[1], a[2], a[3], addr);
                #pragma unroll
                for (int nt = 0; nt < 4; nt++)
                    mma_bf16(c[mt][nt], a, bf[nt >> 1][(nt & 1)*2], bf[nt >> 1][(nt & 1)*2 + 1]);
            }
        }
        __syncthreads();
    }

    const float* __restrict__ msrow = (term == 0) ? g_ms_l2r[bh] : g_ms_r2l[bh];
    float lsum = 0.f;
    #pragma unroll
    for (int nt = 0; nt < 4; nt++) {
        #pragma unroll
        for (int jj = 0; jj < 2; jj++) {
            int u = u0 + wn*32 + nt*8 + (lane & 3)*2 + jj;
            float mk = (msrow[u] > 0.1f) ? 1.f : 0.f;
            #pragma unroll
            for (int mt = 0; mt < 4; mt++) {
                #pragma unroll
                for (int hh = 0; hh < 2; hh++) {
                    int w = w0 + wm*64 + mt*16 + (lane >> 2) + hh*8;
                    float dv = c[mt][nt][hh*2 + jj];
                    lsum += mk * fabsf(dv - ((w == u) ? 1.f : 0.f));
                }
            }
        }
    }
    red[tid] = lsum; __syncthreads();
    for (int s = 128; s; s >>= 1) { if (tid < s) red[tid] += red[tid+s]; __syncthreads(); }
    if (!tid) g_p_cyc[z*9 + blockIdx.y*3 + blockIdx.x] = red[0];
}

// ================= K6: outputs via warp MMA (bf16) =================
__global__ void __launch_bounds__(256) k6_mma(const float* __restrict__ x,
                                              const float* __restrict__ bg,
                                              float* __restrict__ out, int side)
{
    __shared__ __align__(16) __nv_bfloat16 As[128][APAD];
    __shared__ __align__(16) __nv_bfloat16 Bs[64][APAD];
    const int bh = blockIdx.y;
    const int b = bh / Hh, h = bh % Hh;
    const int w0 = blockIdx.x * 128;
    const int tid = threadIdx.x, wid = tid >> 5, lane = tid & 31;
    const int wm = wid >> 2, wn = wid & 3;
    const __nv_bfloat16* __restrict__ Ag = side == 0 ? &b_Mr2l[bh][w0][0] : &b_MLTT[bh][w0][0];
    const __nv_bfloat16* __restrict__ Bg = &b_VT[side == 0 ? 1 : 0][bh][0][0];

    float c[4][2][4];
    #pragma unroll
    for (int mt = 0; mt < 4; mt++)
        #pragma unroll
        for (int nt = 0; nt < 2; nt++)
            #pragma unroll
            for (int i = 0; i < 4; i++) c[mt][nt][i] = 0.f;

    const u32 a_base = smem_u32(As), b_base = smem_u32(Bs);
    const u32 a_row = wm*64 + (lane & 15);
    const u32 a_coff = (lane >> 4) * 16;
    const u32 b_row = wn*16 + (lane & 7) + ((lane >> 4) << 3);
    const u32 b_coff = ((lane >> 3) & 1) * 16;

    for (int ch = 0; ch < 12; ch++) {
        #pragma unroll
        for (int p = 0; p < 2; p++) {
            int idx = tid + p*256;
            int row = idx >> 2, seg = idx & 3;
            uint4 va = *(const uint4*)(Ag + (long)row*Ww + ch*32 + seg*8);
            *(uint2*)&As[row][seg*8]     = make_uint2(va.x, va.y);
            *(uint2*)&As[row][seg*8 + 4] = make_uint2(va.z, va.w);
        }
        {
            int row = tid >> 2, seg = tid & 3;
            uint4 vb = *(const uint4*)(Bg + (long)row*Ww + ch*32 + seg*8);
            *(uint2*)&Bs[row][seg*8]     = make_uint2(vb.x, vb.y);
            *(uint2*)&Bs[row][seg*8 + 4] = make_uint2(vb.z, vb.w);
        }
        __syncthreads();
        #pragma unroll
        for (int ks = 0; ks < 2; ks++) {
            const u32 kb = ks*32;
            u32 bfr[4];
            ldsm4(bfr[0], bfr[1], bfr[2], bfr[3], b_base + b_row*(APAD*2) + kb + b_coff);
            #pragma unroll
            for (int mt = 0; mt < 4; mt++) {
                u32 a[4];
                ldsm4(a[0], a[1], a[2], a[3], a_base + (a_row + mt*16)*(APAD*2) + kb + a_coff);
                mma_bf16(c[mt][0], a, bfr[0], bfr[1]);
                mma_bf16(c[mt][1], a, bfr[2], bfr[3]);
            }
        }
        __syncthreads();
    }

    #pragma unroll
    for (int nt = 0; nt < 2; nt++) {
        #pragma unroll
        for (int jj = 0; jj < 2; jj++) {
            int cc = wn*16 + nt*8 + (lane & 3)*2 + jj;
            float bgc = bg[cc];
            #pragma unroll
            for (int mt = 0; mt < 4; mt++) {
                #pragma unroll
                for (int hh = 0; hh < 2; hh++) {
                    int w = w0 + wm*64 + mt*16 + (lane >> 2) + hh*8;
                    long gi = (((long)b*Cc + cc)*Hh + h)*Ww + w;
                    out[gi] = x[gi] + bgc * c[mt][nt][hh*2 + jj];
                }
            }
        }
    }
}

// ================= K7a: photo term 1 (bf16 M) =================
__global__ void k7a_photo1(const float* __restrict__ LRl, const float* __restrict__ LRr)
{
    __shared__ float lr[3][Ww];
    __shared__ float r8[8];
    const int bh = blockIdx.y;
    const int b = bh / Hh, h = bh % Hh;
    const int w = blockIdx.x*8 + (threadIdx.x >> 5);
    const int lane = threadIdx.x & 31;
    for (int idx = threadIdx.x; idx < 3*Ww; idx += 256) {
        int ch = idx / Ww, v = idx % Ww;
        lr[ch][v] = LRr[(((long)b*3 + ch)*Hh + h)*Ww + v];
    }
    __syncthreads();
    float a0 = 0.f, a1 = 0.f, a2 = 0.f;
    const __nv_bfloat16* __restrict__ mrow = b_Mr2l[bh][w];
    for (int v = lane; v < Ww; v += 32) {
        float m = __bfloat162float(mrow[v]);
        a0 += m*lr[0][v]; a1 += m*lr[1][v]; a2 += m*lr[2][v];
    }
    #pragma unroll
    for (int o = 16; o; o >>= 1) {
        a0 += __shfl_xor_sync(0xffffffffu, a0, o);
        a1 += __shfl_xor_sync(0xffffffffu, a1, o);
        a2 += __shfl_xor_sync(0xffffffffu, a2, o);
    }
    if (!lane) {
        float mk = (g_ms_l2r[bh][w] > 0.1f) ? 1.f : 0.f;
        long base = (((long)b*3)*Hh + h)*Ww + w;
        float part = mk * (fabsf(LRl[base] - a0)
                         + fabsf(LRl[base + (long)Hh*Ww] - a1)
                         + fabsf(LRl[base + 2L*Hh*Ww] - a2));
        r8[threadIdx.x >> 5] = part;
    }
    __syncthreads();
    if (threadIdx.x == 0) {
        float s = 0.f;
        for (int k = 0; k < 8; k++) s += r8[k];
        g_p_ph1[bh*48 + blockIdx.x] = s;
    }
}

// ================= K7b: photo term 2 (bf16 M) =================
__global__ void k7b_photo2(const float* __restrict__ LRl, const float* __restrict__ LRr)
{
    __shared__ float la[3][Ww], lb[3][Ww];
    __shared__ float red[128];
    const int bh = blockIdx.x;
    const int b = bh / Hh, h = bh % Hh;
    const int tid = threadIdx.x;
    for (int idx = tid; idx < 3*Ww; idx += 128) {
        int ch = idx / Ww, w = idx % Ww;
        long gi = (((long)b*3 + ch)*Hh + h)*Ww + w;
        la[ch][w] = LRl[gi];
        lb[ch][w] = LRr[gi];
    }
    __syncthreads();
    float acc[3][3] = {};
    for (int v = 0; v < Ww; v++) {
        const __nv_bfloat16* __restrict__ mr = b_MLT[bh][v];
        float l0 = la[0][v], l1 = la[1][v], l2 = la[2][v];
        #pragma unroll
        for (int s = 0; s < 3; s++) {
            float m = __bfloat162float(mr[tid + s*128]);
            acc[s][0] += m*l0; acc[s][1] += m*l1; acc[s][2] += m*l2;
        }
    }
    float part = 0.f;
    #pragma unroll
    for (int s = 0; s < 3; s++) {
        int w = tid + s*128;
        float mk = (g_ms_r2l[bh][w] > 0.1f) ? 1.f : 0.f;
        part += mk * (fabsf(lb[0][w] - acc[s][0])
                    + fabsf(lb[1][w] - acc[s][1])
                    + fabsf(lb[2][w] - acc[s][2]));
    }
    red[tid] = part; __syncthreads();
    for (int s = 64; s; s >>= 1) { if (tid < s) red[tid] += red[tid+s]; __syncthreads(); }
    if (!tid) g_p_ph2[bh] = red[0];
}

// ================= K8: smoothness (bf16 M) =================
__global__ void k8_smooth()
{
    __shared__ float redh[256], redw[256];
    const int mat = blockIdx.z, bh = blockIdx.y, w0 = blockIdx.x*16;
    const int h = bh % Hh;
    const __nv_bfloat16* __restrict__ M = mat ? &b_MLT[0][0][0] : &b_Mr2l[0][0][0];
    const int tid = threadIdx.x;
    float sh = 0.f, sw = 0.f;
    for (int idx = tid; idx < 16*Ww; idx += 256) {
        int w = w0 + idx / Ww, v = idx % Ww;
        long base = ((long)bh*Ww + w)*Ww + v;
        float m = __bfloat162float(M[base]);
        if (h < Hh - 1) sh += fabsf(m - __bfloat162float(M[base + (long)Ww*Ww]));
        if (w < Ww - 1 && v < Ww - 1) sw += fabsf(m - __bfloat162float(M[base + Ww + 1]));
    }
    redh[tid] = sh; redw[tid] = sw; __syncthreads();
    for (int s = 128; s; s >>= 1) {
        if (tid < s) { redh[tid] += redh[tid+s]; redw[tid] += redw[tid+s]; }
        __syncthreads();
    }
    if (!tid) {
        int slot = (mat*BHn + bh)*24 + blockIdx.x;
        g_p_smh[slot] = redh[0];
        g_p_smw[slot] = redw[0];
    }
}

// ================= K9 =================
__global__ void k9_final(const float* __restrict__ loss_in, float* __restrict__ out_loss)
{
    __shared__ double red[256];
    const int tid = threadIdx.x;
    double acc[4] = {0.0, 0.0, 0.0, 0.0};
    for (int i = tid; i < NP_CYC; i += 256) acc[0] += (double)g_p_cyc[i];
    for (int i = tid; i < NP_PH1; i += 256) acc[1] += (double)g_p_ph1[i];
    for (int i = tid; i < NP_PH2; i += 256) acc[1] += (double)g_p_ph2[i];
    for (int i = tid; i < NP_SM;  i += 256) acc[2] += (double)g_p_smh[i];
    for (int i = tid; i < NP_SM;  i += 256) acc[3] += (double)g_p_smw[i];
    double tot[4];
    for (int a = 0; a < 4; a++) {
        red[tid] = acc[a]; __syncthreads();
        for (int s = 128; s; s >>= 1) { if (tid < s) red[tid] += red[tid+s]; __syncthreads(); }
        tot[a] = red[0]; __syncthreads();
    }
    if (!tid) {
        double lc = tot[0] / ((double)Bz*Hh*Ww*Ww);
        double lp = tot[1] / ((double)Bz*3*Hh*Ww);
        double lh = tot[2] / ((double)Bz*(Hh-1)*Ww*Ww);
        double lw = tot[3] / ((double)Bz*Hh*(Ww-1)*(Ww-1));
        out_loss[0] = (float)((double)loss_in[0] + 0.0025*(lp + 0.1*(lw + lh) + lc));
    }
}

extern "C" void kernel_launch(void* const* d_in, const int* in_sizes, int n_in,
                              void* d_out, int out_size)
{
    (void)in_sizes; (void)n_in; (void)out_size;
    const float* x_l   = (const float*)d_in[0];
    const float* x_r   = (const float*)d_in[1];
    const float* LRl   = (const float*)d_in[2];
    const float* LRr   = (const float*)d_in[3];
    const float* lossi = (const float*)d_in[4];
    const float* nlw = (const float*)d_in[5];
    const float* nlb = (const float*)d_in[6];
    const float* nrw = (const float*)d_in[7];
    const float* nrb = (const float*)d_in[8];
    const float* lp1w = (const float*)d_in[9];
    const float* lp1b = (const float*)d_in[10];
    const float* rp1w = (const float*)d_in[11];
    const float* rp1b = (const float*)d_in[12];
    const float* lp2w = (const float*)d_in[13];
    const float* lp2b = (const float*)d_in[14];
    const float* rp2w = (const float*)d_in[15];
    const float* rp2b = (const float*)d_in[16];
    const float* beta  = (const float*)d_in[17];
    const float* gamma = (const float*)d_in[18];

    float* out = (float*)d_out;
    float* out_xl   = out;
    float* out_xr   = out + NX;
    float* out_lrl  = out + 2L*NX;
    float* out_lrr  = out + 2L*NX + NLR;
    float* out_loss = out + 2L*NX + 2L*NLR;

    const size_t smem1 = (size_t)(Cc*PIX + 2*Cc*Cc + 2*Cc + 2*PIX) * sizeof(float);
    cudaFuncSetAttribute(k1_lnproj, cudaFuncAttributeMaxDynamicSharedMemorySize, (int)smem1);

    k1_lnproj<<<dim3(2, BHn), 256, smem1>>>(x_l, nlw, nlb, lp1w, lp1b, lp2w, lp2b, 0);
    k1_lnproj<<<dim3(2, BHn), 256, smem1>>>(x_r, nrw, nrb, rp1w, rp1b, rp2w, rp2b, 1);
    k2_attn<<<dim3(3, 3, BHn), 256>>>();
    k3a_rowstats<<<dim3(48, BHn), 256>>>();
    k3b_colstats<<<dim3(12, BHn), 256>>>();
    k4_writeM<<<dim3(48, BHn), 256>>>();
    k4t_transpose<<<dim3(6, 6, BHn), 256>>>();
    k5_cycle_mma<<<dim3(3, 3, BHn*2), 256>>>();
    k6_mma<<<dim3(3, BHn), 256>>>(x_l, beta, out_xl, 0);
    k6_mma<<<dim3(3, BHn), 256>>>(x_r, gamma, out_xr, 1);
    k7a_photo1<<<dim3(48, BHn), 256>>>(LRl, LRr);
    k7b_photo2<<<BHn, 128>>>(LRl, LRr);
    k8_smooth<<<dim3(24, BHn, 2), 256>>>();
    cudaMemcpyAsync(out_lrl, LRl, (size_t)NLR*sizeof(float), cudaMemcpyDeviceToDevice, 0);
    cudaMemcpyAsync(out_lrr, LRr, (size_t)NLR*sizeof(float), cudaMemcpyDeviceToDevice, 0);
    k9_final<<<1, 256>>>(lossi, out_loss);
}